// round 11
// baseline (speedup 1.0000x reference)
#include <cuda_runtime.h>
#include <cuda_bf16.h>
#include <cstdint>

#define B_DIM 4096
#define N_CIT 16
#define D_IN  1024
#define D_OUT 1024
#define KTOT  (N_CIT * D_IN)
#define EPSV  0.01f
#define LSPLIT 4
#define QM    16255.f

__device__ float g_lpart[LSPLIT * B_DIM * 256];
__device__ float g_power [B_DIM * 16];
__device__ float g_pxm   [B_DIM * 16];
__device__ float g_xmax  [B_DIM];
__device__ float g_wmax  [D_OUT];
__device__ __align__(16) int8_t g_x1[(size_t)B_DIM * D_IN];
__device__ __align__(16) int8_t g_x0[(size_t)B_DIM * D_IN];
__device__ __align__(16) int8_t g_w1[(size_t)D_OUT * KTOT];
__device__ __align__(16) int8_t g_w0[(size_t)D_OUT * KTOT];
__device__ __nv_bfloat16 g_wd_hi[256 * D_IN];
__device__ __nv_bfloat16 g_wd_lo[256 * D_IN];

__device__ __forceinline__ uint32_t smem_to_u32(const void* p) {
    uint32_t a;
    asm("{ .reg .u64 t; cvta.to.shared.u64 t, %1; cvt.u32.u64 %0, t; }" : "=r"(a) : "l"(p));
    return a;
}
__device__ __forceinline__ uint32_t sw(uint32_t base, int row, int q) {
    return base + row * 64 + (((uint32_t)(q ^ ((row >> 1) & 3))) << 4);
}
__device__ __forceinline__ uint32_t pack_bf16(float f0, float f1) {
    uint32_t r;
    asm("cvt.rn.bf16x2.f32 %0, %1, %2;" : "=r"(r) : "f"(f1), "f"(f0));
    return r;
}
#define CP_ASYNC16(dst, src) \
    asm volatile("cp.async.cg.shared.global [%0], [%1], 16;" :: "r"(dst), "l"(src) : "memory")
#define CP_COMMIT() asm volatile("cp.async.commit_group;" ::: "memory")
#define CP_WAIT0()  asm volatile("cp.async.wait_group 0;" ::: "memory")
#define LDSM4(r, addr) \
    asm volatile("ldmatrix.sync.aligned.m8n8.x4.shared.b16 {%0,%1,%2,%3}, [%4];" \
        : "=r"((r)[0]), "=r"((r)[1]), "=r"((r)[2]), "=r"((r)[3]) : "r"(addr))
#define MMA_BF16(d, a, b) \
    asm volatile("mma.sync.aligned.m16n8k16.row.col.f32.bf16.bf16.f32 " \
        "{%0,%1,%2,%3}, {%4,%5,%6,%7}, {%8,%9}, {%0,%1,%2,%3};" \
        : "+f"((d)[0]), "+f"((d)[1]), "+f"((d)[2]), "+f"((d)[3]) \
        : "r"((a)[0]), "r"((a)[1]), "r"((a)[2]), "r"((a)[3]), "r"((b)[0]), "r"((b)[1]))
#define MMA_S8(d, a, b) \
    asm volatile("mma.sync.aligned.m16n8k32.row.col.s32.s8.s8.s32 " \
        "{%0,%1,%2,%3}, {%4,%5,%6,%7}, {%8,%9}, {%0,%1,%2,%3};" \
        : "+r"((d)[0]), "+r"((d)[1]), "+r"((d)[2]), "+r"((d)[3]) \
        : "r"((a)[0]), "r"((a)[1]), "r"((a)[2]), "r"((a)[3]), "r"((b)[0]), "r"((b)[1]))
#define STS128(addr, r0, r1, r2, r3) \
    asm volatile("st.shared.v4.b32 [%0], {%1,%2,%3,%4};" \
        :: "r"(addr), "r"(r0), "r"(r1), "r"(r2), "r"(r3) : "memory")

// ============================================================================
// Q1: quantize x rows -> g_x1/g_x0 + g_xmax. One warp per row.
// ============================================================================
__global__ __launch_bounds__(256) void xq_kernel(const float* __restrict__ x)
{
    const int row = blockIdx.x * 8 + (threadIdx.x >> 5);
    const int lane = threadIdx.x & 31;
    const float* xr = x + (size_t)row * D_IN;

    float m = 0.f;
    for (int i = lane; i < 256; i += 32) {
        float4 v = ((const float4*)xr)[i];
        m = fmaxf(m, fmaxf(fmaxf(fabsf(v.x), fabsf(v.y)),
                           fmaxf(fabsf(v.z), fabsf(v.w))));
    }
    #pragma unroll
    for (int o = 16; o >= 1; o >>= 1) m = fmaxf(m, __shfl_xor_sync(0xffffffffu, m, o));
    m = fmaxf(m, 1e-30f);
    if (lane == 0) g_xmax[row] = m;
    const float s = QM / m;

    const int base = lane * 32;
    uint32_t p1[8], p0[8];
    #pragma unroll
    for (int i = 0; i < 8; i++) {
        float4 v = *(const float4*)(xr + base + i * 4);
        float f[4] = {v.x, v.y, v.z, v.w};
        uint32_t w1 = 0, w0 = 0;
        #pragma unroll
        for (int e = 0; e < 4; e++) {
            int X = __float2int_rn(f[e] * s);
            int X1 = (X + 64) >> 7;
            int X0 = X - (X1 << 7);
            w1 |= (uint32_t)(X1 & 0xFF) << (e * 8);
            w0 |= (uint32_t)(X0 & 0xFF) << (e * 8);
        }
        p1[i] = w1; p0[i] = w0;
    }
    size_t dst = (size_t)row * D_IN + base;
    *(uint4*)&g_x1[dst]      = make_uint4(p1[0], p1[1], p1[2], p1[3]);
    *(uint4*)&g_x1[dst + 16] = make_uint4(p1[4], p1[5], p1[6], p1[7]);
    *(uint4*)&g_x0[dst]      = make_uint4(p0[0], p0[1], p0[2], p0[3]);
    *(uint4*)&g_x0[dst + 16] = make_uint4(p0[4], p0[5], p0[6], p0[7]);
}

__global__ void wmax_zero() {
    g_wmax[blockIdx.x * 256 + threadIdx.x] = 0.f;
}

__global__ __launch_bounds__(256) void wq_max(const float* __restrict__ Wy)
{
    const int col = blockIdx.x * 64 + (threadIdx.x & 63);
    const int rg = threadIdx.x >> 6;
    const int k0 = blockIdx.y * 2048;
    float m = 0.f;
    for (int k = k0 + rg; k < k0 + 2048; k += 4)
        m = fmaxf(m, fabsf(Wy[(size_t)k * D_OUT + col]));
    atomicMax((int*)&g_wmax[col], __float_as_int(m));
}

// ============================================================================
// Q3: transpose + 2-digit int8 quantize Wy -> g_w1/g_w0 [o][k]
// ============================================================================
__global__ __launch_bounds__(256) void wq_pack(const float* __restrict__ Wy)
{
    __shared__ float T[64][65];
    const int k0 = blockIdx.x * 64;
    const int o0 = blockIdx.y * 64;
    const int tid = threadIdx.x;
    {
        int kr = tid >> 4, o4 = tid & 15;
        #pragma unroll
        for (int r = 0; r < 4; r++) {
            int k = kr + r * 16;
            float4 v = *(const float4*)&Wy[(size_t)(k0 + k) * D_OUT + o0 + o4 * 4];
            T[k][o4 * 4 + 0] = v.x;  T[k][o4 * 4 + 1] = v.y;
            T[k][o4 * 4 + 2] = v.z;  T[k][o4 * 4 + 3] = v.w;
        }
    }
    __syncthreads();
    {
        int o = tid >> 2, kq = tid & 3;
        float s = QM / fmaxf(g_wmax[o0 + o], 1e-30f);
        uint32_t w1[4], w0[4];
        #pragma unroll
        for (int g4 = 0; g4 < 4; g4++) {
            uint32_t a1 = 0, a0 = 0;
            #pragma unroll
            for (int e = 0; e < 4; e++) {
                int X = __float2int_rn(T[kq * 16 + g4 * 4 + e][o] * s);
                int X1 = (X + 64) >> 7;
                int X0 = X - (X1 << 7);
                a1 |= (uint32_t)(X1 & 0xFF) << (e * 8);
                a0 |= (uint32_t)(X0 & 0xFF) << (e * 8);
            }
            w1[g4] = a1; w0[g4] = a0;
        }
        size_t dst = (size_t)(o0 + o) * KTOT + k0 + kq * 16;
        *(uint4*)&g_w1[dst] = make_uint4(w1[0], w1[1], w1[2], w1[3]);
        *(uint4*)&g_w0[dst] = make_uint4(w0[0], w0[1], w0[2], w0[3]);
    }
}

// ============================================================================
// wd_prep + logits (split-bf16 path, unchanged from round 9 best)
// ============================================================================
__global__ __launch_bounds__(256) void wd_prep(const float* __restrict__ Wd)
{
    const int c = blockIdx.x;
    const int n = c >> 4, j = c & 15;
    const int tid = threadIdx.x;
    const float* src = Wd + (size_t)n * (D_IN * 16) + j;
    int k = tid * 4;
    float a0 = src[(size_t)(k + 0) * 16];
    float a1 = src[(size_t)(k + 1) * 16];
    float a2 = src[(size_t)(k + 2) * 16];
    float a3 = src[(size_t)(k + 3) * 16];
    uint32_t h0 = pack_bf16(a0, a1);
    uint32_t h1 = pack_bf16(a2, a3);
    float f0 = __uint_as_float(h0 << 16);
    float f1 = __uint_as_float(h0 & 0xFFFF0000u);
    float f2 = __uint_as_float(h1 << 16);
    float f3 = __uint_as_float(h1 & 0xFFFF0000u);
    *(uint2*)&g_wd_hi[(size_t)c * D_IN + k] = make_uint2(h0, h1);
    *(uint2*)&g_wd_lo[(size_t)c * D_IN + k] =
        make_uint2(pack_bf16(a0 - f0, a1 - f1), pack_bf16(a2 - f2, a3 - f3));
}

__device__ __forceinline__ void math_kh(uint32_t cb, int kh, int wm, int wn,
                                        int j, int rr, float acc[4][8][4])
{
    uint32_t afh[4][4], afl[4][4];
    #pragma unroll
    for (int t = 0; t < 4; t++) {
        int row = wm + t * 16 + ((j & 1) << 3) + rr;
        int q = kh * 2 + (j >> 1);
        LDSM4(afh[t], sw(cb, row, q));
        LDSM4(afl[t], sw(cb + 8192, row, q));
    }
    #pragma unroll
    for (int uh = 0; uh < 2; uh++) {
        uint32_t bfh[4][2], bfl[4][2];
        #pragma unroll
        for (int up = 0; up < 2; up++) {
            int u0 = uh * 4 + up * 2;
            int nrow = wn + u0 * 8 + ((j >> 1) << 3) + rr;
            int q = kh * 2 + (j & 1);
            uint32_t t4[4];
            LDSM4(t4, sw(cb + 16384, nrow, q));
            bfh[up * 2][0] = t4[0]; bfh[up * 2][1] = t4[1];
            bfh[up * 2 + 1][0] = t4[2]; bfh[up * 2 + 1][1] = t4[3];
            LDSM4(t4, sw(cb + 32768, nrow, q));
            bfl[up * 2][0] = t4[0]; bfl[up * 2][1] = t4[1];
            bfl[up * 2 + 1][0] = t4[2]; bfl[up * 2 + 1][1] = t4[3];
        }
        #pragma unroll
        for (int t = 0; t < 4; t++)
            #pragma unroll
            for (int uu = 0; uu < 4; uu++)
                MMA_BF16(acc[t][uh * 4 + uu], afh[t], bfh[uu]);
        #pragma unroll
        for (int t = 0; t < 4; t++)
            #pragma unroll
            for (int uu = 0; uu < 4; uu++)
                MMA_BF16(acc[t][uh * 4 + uu], afh[t], bfl[uu]);
        #pragma unroll
        for (int t = 0; t < 4; t++)
            #pragma unroll
            for (int uu = 0; uu < 4; uu++)
                MMA_BF16(acc[t][uh * 4 + uu], afl[t], bfh[uu]);
    }
}

#define BUFSTRIDE 49152
#define GSMEM_TOTAL (2 * BUFSTRIDE)
#define LSTG (D_IN / 32 / LSPLIT)

__device__ __forceinline__ void cp_b_logits(uint32_t buf, int kc, int tid)
{
    size_t off = ((size_t)tid * D_IN + (size_t)kc * 32) * 2;
    const char* sh = (const char*)g_wd_hi + off;
    const char* sl = (const char*)g_wd_lo + off;
    uint32_t bh = buf + 16384, bl = buf + 32768;
    #pragma unroll
    for (int q = 0; q < 4; q++) {
        CP_ASYNC16(sw(bh, tid, q), sh + q * 16);
        CP_ASYNC16(sw(bl, tid, q), sl + q * 16);
    }
}

__device__ __forceinline__ void gen_a_logits(uint32_t buf, const float* __restrict__ x,
                                             int bm, int kc, int tid)
{
    const int ar = tid >> 1;
    const int half = tid & 1;
    float v[16];
    const float* xp = x + (size_t)(bm + ar) * D_IN + kc * 32 + half * 16;
    #pragma unroll
    for (int q = 0; q < 4; q++) {
        float4 t4 = *(const float4*)(xp + q * 4);
        v[q * 4 + 0] = t4.x; v[q * 4 + 1] = t4.y;
        v[q * 4 + 2] = t4.z; v[q * 4 + 3] = t4.w;
    }
    #pragma unroll
    for (int q2 = 0; q2 < 2; q2++) {
        uint32_t hi4[4], lo4[4];
        #pragma unroll
        for (int i = 0; i < 4; i++) {
            float f0 = v[q2 * 8 + i * 2];
            float f1 = v[q2 * 8 + i * 2 + 1];
            uint32_t hb = pack_bf16(f0, f1);
            float fh0 = __uint_as_float(hb << 16);
            float fh1 = __uint_as_float(hb & 0xFFFF0000u);
            hi4[i] = hb;
            lo4[i] = pack_bf16(f0 - fh0, f1 - fh1);
        }
        int q = half * 2 + q2;
        STS128(sw(buf, ar, q),        hi4[0], hi4[1], hi4[2], hi4[3]);
        STS128(sw(buf + 8192, ar, q), lo4[0], lo4[1], lo4[2], lo4[3]);
    }
}

__global__ __launch_bounds__(256, 1) void logits_mma(const float* __restrict__ x)
{
    extern __shared__ char smem[];
    const uint32_t sb = smem_to_u32(smem);
    const int tid = threadIdx.x;
    const int lane = tid & 31, w = tid >> 5;
    const int ks = blockIdx.x;
    const int bm = blockIdx.y * 128;
    const int wm = (w & 1) * 64, wn = (w >> 1) * 64;
    const int kc0 = ks * LSTG;

    float acc[4][8][4];
    #pragma unroll
    for (int t = 0; t < 4; t++)
        #pragma unroll
        for (int u = 0; u < 8; u++)
            #pragma unroll
            for (int c = 0; c < 4; c++) acc[t][u][c] = 0.f;

    cp_b_logits(sb, kc0, tid);
    CP_COMMIT();
    gen_a_logits(sb, x, bm, kc0, tid);
    CP_WAIT0();
    __syncthreads();

    const int j = lane >> 3, rr = lane & 7;
    for (int s = 0; s < LSTG; s++) {
        const uint32_t cb = sb + (uint32_t)(s & 1) * BUFSTRIDE;
        const uint32_t nb = sb + (uint32_t)((s + 1) & 1) * BUFSTRIDE;
        const bool has_next = (s + 1 < LSTG);
        if (has_next) { cp_b_logits(nb, kc0 + s + 1, tid); CP_COMMIT(); }
        math_kh(cb, 0, wm, wn, j, rr, acc);
        if (has_next) gen_a_logits(nb, x, bm, kc0 + s + 1, tid);
        math_kh(cb, 1, wm, wn, j, rr, acc);
        if (has_next) CP_WAIT0();
        __syncthreads();
    }

    float* lp = g_lpart + (size_t)ks * (B_DIM * 256);
    #pragma unroll
    for (int t = 0; t < 4; t++) {
        int row0 = bm + wm + t * 16 + (lane >> 2);
        #pragma unroll
        for (int u = 0; u < 8; u++) {
            int col = wn + u * 8 + (lane & 3) * 2;
            *(float2*)&lp[(size_t)row0 * 256 + col] =
                make_float2(acc[t][u][0], acc[t][u][1]);
            *(float2*)&lp[(size_t)(row0 + 8) * 256 + col] =
                make_float2(acc[t][u][2], acc[t][u][3]);
        }
    }
}

// ============================================================================
// power: sum partials + bd, softmax + warp-parallel 16x16 solve; writes pxm too
// ============================================================================
__global__ __launch_bounds__(256) void power_kernel(const float* __restrict__ bd)
{
    const int tid = threadIdx.x;
    const int lane = tid & 31;
    const int l16 = lane & 15;
    const int b = blockIdx.x * 16 + (tid >> 4);
    const float ome = 1.f - EPSV;

    float d[16];
    {
        size_t base = (size_t)b * 256 + l16 * 16;
        #pragma unroll
        for (int q = 0; q < 4; q++) {
            float4 t0 = *(const float4*)(g_lpart + base + q * 4);
            float4 t1 = *(const float4*)(g_lpart + (size_t)1 * B_DIM * 256 + base + q * 4);
            float4 t2 = *(const float4*)(g_lpart + (size_t)2 * B_DIM * 256 + base + q * 4);
            float4 t3 = *(const float4*)(g_lpart + (size_t)3 * B_DIM * 256 + base + q * 4);
            float4 bb = *(const float4*)(bd + l16 * 16 + q * 4);
            d[q * 4 + 0] = t0.x + t1.x + t2.x + t3.x + bb.x;
            d[q * 4 + 1] = t0.y + t1.y + t2.y + t3.y + bb.y;
            d[q * 4 + 2] = t0.z + t1.z + t2.z + t3.z + bb.z;
            d[q * 4 + 3] = t0.w + t1.w + t2.w + t3.w + bb.w;
        }
        float mx = d[0];
        #pragma unroll
        for (int j = 1; j < 16; j++) mx = fmaxf(mx, d[j]);
        float s = 0.f;
        #pragma unroll
        for (int j = 0; j < 16; j++) { d[j] = expf(d[j] - mx); s += d[j]; }
        float inv = 1.f / s;
        #pragma unroll
        for (int j = 0; j < 16; j++) d[j] *= inv;
    }

    #pragma unroll
    for (int m = 1; m < 16; m <<= 1) {
        float u[16];
        #pragma unroll
        for (int i = 0; i < 16; i++)
            u[i] = __shfl_xor_sync(0xffffffffu, d[i ^ m], m);
        #pragma unroll
        for (int i = 0; i < 16; i++)
            if ((i & m) != (l16 & m)) d[i] = u[i];
    }

    float diag = 0.f;
    #pragma unroll
    for (int i = 0; i < 16; i++)
        if (i == l16) diag = d[i];

    float row[17];
    #pragma unroll
    for (int n = 0; n < 16; n++)
        row[n] = (n == l16) ? 1.f : -ome * d[n];
    row[16] = 1.f;

    #pragma unroll
    for (int p = 0; p < 16; p++) {
        float pivot = __shfl_sync(0xffffffffu, row[p], p, 16);
        float inv = 1.f / pivot;
        float f = row[p];
        #pragma unroll
        for (int c = p; c < 17; c++) {
            float pc = __shfl_sync(0xffffffffu, row[c], p, 16) * inv;
            if (l16 == p)      row[c] = pc;
            else if (l16 > p)  row[c] -= f * pc;
        }
    }

    float s = row[16];
    float z = 0.f;
    #pragma unroll
    for (int r = 15; r >= 0; r--) {
        float zr = __shfl_sync(0xffffffffu, s, r, 16);
        if (l16 == r) z = zr;
        if (l16 < r)  s -= row[r] * zr;
    }

    float zs = z;
    #pragma unroll
    for (int m = 8; m >= 1; m >>= 1)
        zs += __shfl_xor_sync(0xffffffffu, zs, m);
    float z16 = 1.f + EPSV * zs;
    float add = z16 * (1.f / 16.f) - (1.f / 16.f);
    float pw = z * ome * diag + add;
    g_power[(size_t)b * 16 + l16] = pw;
    g_pxm[(size_t)b * 16 + l16] = pw * g_xmax[b];
}

// ============================================================================
// main_i8: int8 split-digit GEMM. CTA 128x128, warp 64x32, K-chunk 32.
// SMEM: 2 x [A 8KB | B 8KB] + fp32 master 128x132
// ============================================================================
#define IBUF 16384
#define MOFF 32768
#define MSTRIDE 132
#define ISMEM_TOTAL (MOFF + 128 * MSTRIDE * 4)

__device__ __forceinline__ void cp_i8(uint32_t buf, int bm, int bn, int s, int tid)
{
    const int n = s >> 5, kc = s & 31;
    const int row = tid & 127;
    const int8_t *s1, *s0;
    uint32_t dst;
    if (tid < 128) {
        size_t o = (size_t)(bm + row) * D_IN + kc * 32;
        s1 = g_x1 + o; s0 = g_x0 + o;
        dst = buf;
    } else {
        size_t o = (size_t)(bn + row) * KTOT + n * 1024 + kc * 32;
        s1 = g_w1 + o; s0 = g_w0 + o;
        dst = buf + 8192;
    }
    CP_ASYNC16(sw(dst, row, 0), s1);
    CP_ASYNC16(sw(dst, row, 1), s1 + 16);
    CP_ASYNC16(sw(dst, row, 2), s0);
    CP_ASYNC16(sw(dst, row, 3), s0 + 16);
}

__global__ __launch_bounds__(256, 1) void main_i8(
    const float* __restrict__ by, float* __restrict__ out)
{
    extern __shared__ char smem[];
    const uint32_t sb = smem_to_u32(smem);
    float* msmem = (float*)(smem + MOFF);
    const int tid = threadIdx.x;
    const int lane = tid & 31, w = tid >> 5;
    const int bm = blockIdx.y * 128;
    const int bn = blockIdx.x * 128;
    const int wm = (w & 1) * 64, wn = (w >> 1) * 32;

    int hh[4][4][4], xx[4][4][4];
    #pragma unroll
    for (int t = 0; t < 4; t++)
        #pragma unroll
        for (int u = 0; u < 4; u++)
            #pragma unroll
            for (int e = 0; e < 4; e++) { hh[t][u][e] = 0; xx[t][u][e] = 0; }

    for (int i = tid; i < 128 * MSTRIDE; i += 256) msmem[i] = 0.f;

    cp_i8(sb, bm, bn, 0, tid);
    CP_COMMIT();
    CP_WAIT0();
    __syncthreads();

    const int j = lane >> 3, rr = lane & 7;

    for (int s = 0; s < 512; s++) {
        const uint32_t cb = sb + (uint32_t)(s & 1) * IBUF;
        const bool has_next = (s + 1 < 512);

        if (has_next) {
            cp_i8(sb + (uint32_t)((s + 1) & 1) * IBUF, bm, bn, s + 1, tid);
            CP_COMMIT();
        }

        uint32_t afh[4][4], afl[4][4], bfh[4][2], bfl[4][2];
        const uint32_t cbB = cb + 8192;
        #pragma unroll
        for (int t = 0; t < 4; t++) {
            int row = wm + t * 16 + ((j & 1) << 3) + rr;
            LDSM4(afh[t], sw(cb, row, (j >> 1)));
            LDSM4(afl[t], sw(cb, row, 2 + (j >> 1)));
        }
        #pragma unroll
        for (int g = 0; g < 2; g++) {
            int nrow = wn + g * 16 + ((j >> 1) << 3) + rr;
            uint32_t t4[4];
            LDSM4(t4, sw(cbB, nrow, (j & 1)));
            bfh[g * 2][0] = t4[0]; bfh[g * 2][1] = t4[1];
            bfh[g * 2 + 1][0] = t4[2]; bfh[g * 2 + 1][1] = t4[3];
            LDSM4(t4, sw(cbB, nrow, 2 + (j & 1)));
            bfl[g * 2][0] = t4[0]; bfl[g * 2][1] = t4[1];
            bfl[g * 2 + 1][0] = t4[2]; bfl[g * 2 + 1][1] = t4[3];
        }

        #pragma unroll
        for (int t = 0; t < 4; t++)
            #pragma unroll
            for (int u = 0; u < 4; u++)
                MMA_S8(hh[t][u], afh[t], bfh[u]);
        #pragma unroll
        for (int t = 0; t < 4; t++)
            #pragma unroll
            for (int u = 0; u < 4; u++)
                MMA_S8(xx[t][u], afh[t], bfl[u]);
        #pragma unroll
        for (int t = 0; t < 4; t++)
            #pragma unroll
            for (int u = 0; u < 4; u++)
                MMA_S8(xx[t][u], afl[t], bfh[u]);

        if ((s & 31) == 31) {
            const int n = s >> 5;
            #pragma unroll
            for (int t = 0; t < 4; t++) {
                int rl0 = wm + t * 16 + (lane >> 2);
                int rl1 = rl0 + 8;
                float c0 = 128.f * g_pxm[(size_t)(bm + rl0) * 16 + n];
                float c1 = 128.f * g_pxm[(size_t)(bm + rl1) * 16 + n];
                #pragma unroll
                for (int u = 0; u < 4; u++) {
                    int cl = wn + u * 8 + (lane & 3) * 2;
                    float* m0 = msmem + rl0 * MSTRIDE + cl;
                    float* m1 = msmem + rl1 * MSTRIDE + cl;
                    m0[0] += fmaf(128.f, (float)hh[t][u][0], (float)xx[t][u][0]) * c0;
                    m0[1] += fmaf(128.f, (float)hh[t][u][1], (float)xx[t][u][1]) * c0;
                    m1[0] += fmaf(128.f, (float)hh[t][u][2], (float)xx[t][u][2]) * c1;
                    m1[1] += fmaf(128.f, (float)hh[t][u][3], (float)xx[t][u][3]) * c1;
                    #pragma unroll
                    for (int e = 0; e < 4; e++) { hh[t][u][e] = 0; xx[t][u][e] = 0; }
                }
            }
        }

        if (has_next) CP_WAIT0();
        __syncthreads();
    }

    // epilogue: stage by tile, scale master by wmax/QM^2, add bias
    float* bys = (float*)smem;           // 16 x 128 fp32 = 8KB (buffers free now)
    {
        int L = tid * 8;
        int n = L >> 7, c = L & 127;
        *(float4*)&bys[n * 128 + c]     = *(const float4*)&by[(size_t)n * D_OUT + bn + c];
        *(float4*)&bys[n * 128 + c + 4] = *(const float4*)&by[(size_t)n * D_OUT + bn + c + 4];
    }
    __syncthreads();

    const float qi = 1.f / (QM * QM);
    #pragma unroll
    for (int t = 0; t < 4; t++) {
        int rl0 = wm + t * 16 + (lane >> 2);
        int rl1 = rl0 + 8;
        float p0[16], p1[16];
        #pragma unroll
        for (int q = 0; q < 4; q++) {
            float4 v0 = *(const float4*)&g_power[(size_t)(bm + rl0) * 16 + q * 4];
            float4 v1 = *(const float4*)&g_power[(size_t)(bm + rl1) * 16 + q * 4];
            p0[q*4+0]=v0.x; p0[q*4+1]=v0.y; p0[q*4+2]=v0.z; p0[q*4+3]=v0.w;
            p1[q*4+0]=v1.x; p1[q*4+1]=v1.y; p1[q*4+2]=v1.z; p1[q*4+3]=v1.w;
        }
        #pragma unroll
        for (int u = 0; u < 4; u++) {
            int cl = wn + u * 8 + (lane & 3) * 2;
            float w0 = g_wmax[bn + cl] * qi;
            float w1 = g_wmax[bn + cl + 1] * qi;
            float b00 = 0.f, b01 = 0.f, b10 = 0.f, b11 = 0.f;
            #pragma unroll
            for (int n = 0; n < 16; n++) {
                float by0 = bys[n * 128 + cl], by1 = bys[n * 128 + cl + 1];
                b00 += p0[n] * by0;  b01 += p0[n] * by1;
                b10 += p1[n] * by0;  b11 += p1[n] * by1;
            }
            *(float2*)&out[(size_t)(bm + rl0) * D_OUT + bn + cl] =
                make_float2(msmem[rl0 * MSTRIDE + cl] * w0 + b00,
                            msmem[rl0 * MSTRIDE + cl + 1] * w1 + b01);
            *(float2*)&out[(size_t)(bm + rl1) * D_OUT + bn + cl] =
                make_float2(msmem[rl1 * MSTRIDE + cl] * w0 + b10,
                            msmem[rl1 * MSTRIDE + cl + 1] * w1 + b11);
        }
    }
}

// ============================================================================
extern "C" void kernel_launch(void* const* d_in, const int* in_sizes, int n_in,
                              void* d_out, int out_size)
{
    const float* x  = (const float*)d_in[0];
    const float* Wy = (const float*)d_in[1];
    const float* by = (const float*)d_in[2];
    const float* Wd = (const float*)d_in[3];
    const float* bd = (const float*)d_in[4];
    float* out = (float*)d_out;

    cudaFuncSetAttribute(logits_mma, cudaFuncAttributeMaxDynamicSharedMemorySize,
                         GSMEM_TOTAL);
    cudaFuncSetAttribute(main_i8, cudaFuncAttributeMaxDynamicSharedMemorySize,
                         ISMEM_TOTAL);

    xq_kernel<<<B_DIM / 8, 256>>>(x);
    wmax_zero<<<D_OUT / 256, 256>>>();
    wq_max<<<dim3(D_OUT / 64, KTOT / 2048), 256>>>(Wy);
    wq_pack<<<dim3(KTOT / 64, D_OUT / 64), 256>>>(Wy);
    wd_prep<<<256, 256>>>(Wd);
    logits_mma<<<dim3(LSPLIT, B_DIM / 128), 256, GSMEM_TOTAL>>>(x);
    power_kernel<<<B_DIM / 16, 256>>>(bd);
    main_i8<<<dim3(D_OUT / 128, B_DIM / 128), 256, ISMEM_TOTAL>>>(by, out);
}

// round 12
// speedup vs baseline: 2.8554x; 2.8554x over previous
#include <cuda_runtime.h>
#include <cuda_bf16.h>
#include <cstdint>

#define B_DIM 4096
#define N_CIT 16
#define D_IN  1024
#define D_OUT 1024
#define KTOT  (N_CIT * D_IN)
#define EPSV  0.01f
#define LSPLIT 4

__device__ float g_lpart[LSPLIT * B_DIM * 256];
__device__ float g_power [B_DIM * 16];
__device__ __nv_bfloat16 g_wt_hi[(size_t)D_OUT * KTOT];  // [o][k] K-major
__device__ __nv_bfloat16 g_wt_lo[(size_t)D_OUT * KTOT];
__device__ __nv_bfloat16 g_by_hi[(size_t)D_OUT * 32];    // [o][k] k 0..15 real, rest 0
__device__ __nv_bfloat16 g_by_lo[(size_t)D_OUT * 32];
__device__ __nv_bfloat16 g_wd_hi[256 * D_IN];
__device__ __nv_bfloat16 g_wd_lo[256 * D_IN];

__device__ __forceinline__ uint32_t smem_to_u32(const void* p) {
    uint32_t a;
    asm("{ .reg .u64 t; cvta.to.shared.u64 t, %1; cvt.u32.u64 %0, t; }" : "=r"(a) : "l"(p));
    return a;
}
__device__ __forceinline__ uint32_t sw(uint32_t base, int row, int q) {
    return base + row * 64 + (((uint32_t)(q ^ ((row >> 1) & 3))) << 4);
}
__device__ __forceinline__ uint32_t pack_bf16(float f0, float f1) {
    uint32_t r;
    asm("cvt.rn.bf16x2.f32 %0, %1, %2;" : "=r"(r) : "f"(f1), "f"(f0));
    return r;
}
#define CP_ASYNC16(dst, src) \
    asm volatile("cp.async.cg.shared.global [%0], [%1], 16;" :: "r"(dst), "l"(src) : "memory")
#define CP_COMMIT() asm volatile("cp.async.commit_group;" ::: "memory")
#define CP_WAIT0()  asm volatile("cp.async.wait_group 0;" ::: "memory")
#define LDSM4(r, addr) \
    asm volatile("ldmatrix.sync.aligned.m8n8.x4.shared.b16 {%0,%1,%2,%3}, [%4];" \
        : "=r"((r)[0]), "=r"((r)[1]), "=r"((r)[2]), "=r"((r)[3]) : "r"(addr))
#define MMA_BF16(d, a, b) \
    asm volatile("mma.sync.aligned.m16n8k16.row.col.f32.bf16.bf16.f32 " \
        "{%0,%1,%2,%3}, {%4,%5,%6,%7}, {%8,%9}, {%0,%1,%2,%3};" \
        : "+f"((d)[0]), "+f"((d)[1]), "+f"((d)[2]), "+f"((d)[3]) \
        : "r"((a)[0]), "r"((a)[1]), "r"((a)[2]), "r"((a)[3]), "r"((b)[0]), "r"((b)[1]))
#define STS128(addr, r0, r1, r2, r3) \
    asm volatile("st.shared.v4.b32 [%0], {%1,%2,%3,%4};" \
        :: "r"(addr), "r"(r0), "r"(r1), "r"(r2), "r"(r3) : "memory")

// ============================================================================
// Kernel 0a: transpose + hi/lo bf16 split: Wy[16384,1024] -> g_wt[1024][16384]
// ============================================================================
__global__ __launch_bounds__(256) void transpose_split(const float* __restrict__ Wy)
{
    __shared__ float T[64][65];
    const int k0 = blockIdx.x * 64;
    const int o0 = blockIdx.y * 64;
    const int tid = threadIdx.x;
    {
        int kr = tid >> 4, o4 = tid & 15;
        #pragma unroll
        for (int r = 0; r < 4; r++) {
            int k = kr + r * 16;
            float4 v = *(const float4*)&Wy[(size_t)(k0 + k) * D_OUT + o0 + o4 * 4];
            T[k][o4 * 4 + 0] = v.x;  T[k][o4 * 4 + 1] = v.y;
            T[k][o4 * 4 + 2] = v.z;  T[k][o4 * 4 + 3] = v.w;
        }
    }
    __syncthreads();
    {
        int o = tid >> 2, kq = tid & 3;
        uint32_t hi[8], lo[8];
        #pragma unroll
        for (int i = 0; i < 8; i++) {
            float a = T[kq * 16 + i * 2][o];
            float b = T[kq * 16 + i * 2 + 1][o];
            uint32_t h = pack_bf16(a, b);
            float fha = __uint_as_float(h << 16);
            float fhb = __uint_as_float(h & 0xFFFF0000u);
            hi[i] = h;
            lo[i] = pack_bf16(a - fha, b - fhb);
        }
        size_t dst = (size_t)(o0 + o) * KTOT + k0 + kq * 16;
        *(uint4*)&g_wt_hi[dst]     = make_uint4(hi[0], hi[1], hi[2], hi[3]);
        *(uint4*)&g_wt_hi[dst + 8] = make_uint4(hi[4], hi[5], hi[6], hi[7]);
        *(uint4*)&g_wt_lo[dst]     = make_uint4(lo[0], lo[1], lo[2], lo[3]);
        *(uint4*)&g_wt_lo[dst + 8] = make_uint4(lo[4], lo[5], lo[6], lo[7]);
    }
}

// ============================================================================
// Kernel 0b: by[16][1024] -> g_by[1024][32] bf16 hi/lo (k 16..31 zero)
// ============================================================================
__global__ __launch_bounds__(256) void by_prep(const float* __restrict__ by)
{
    int o = blockIdx.x * 256 + threadIdx.x;
    if (o >= D_OUT) return;
    #pragma unroll
    for (int kp = 0; kp < 8; kp++) {
        float a = by[(size_t)(kp * 2)     * D_OUT + o];
        float b = by[(size_t)(kp * 2 + 1) * D_OUT + o];
        uint32_t h = pack_bf16(a, b);
        float fha = __uint_as_float(h << 16);
        float fhb = __uint_as_float(h & 0xFFFF0000u);
        uint32_t l = pack_bf16(a - fha, b - fhb);
        *(uint32_t*)&g_by_hi[(size_t)o * 32 + kp * 2] = h;
        *(uint32_t*)&g_by_lo[(size_t)o * 32 + kp * 2] = l;
    }
    #pragma unroll
    for (int kp = 8; kp < 16; kp++) {
        *(uint32_t*)&g_by_hi[(size_t)o * 32 + kp * 2] = 0u;
        *(uint32_t*)&g_by_lo[(size_t)o * 32 + kp * 2] = 0u;
    }
}

// ============================================================================
// Kernel 0c: Wd -> g_wd (K-major, hi/lo)
// ============================================================================
__global__ __launch_bounds__(256) void wd_prep(const float* __restrict__ Wd)
{
    const int c = blockIdx.x;
    const int n = c >> 4, j = c & 15;
    const int tid = threadIdx.x;
    const float* src = Wd + (size_t)n * (D_IN * 16) + j;
    int k = tid * 4;
    float a0 = src[(size_t)(k + 0) * 16];
    float a1 = src[(size_t)(k + 1) * 16];
    float a2 = src[(size_t)(k + 2) * 16];
    float a3 = src[(size_t)(k + 3) * 16];
    uint32_t h0 = pack_bf16(a0, a1);
    uint32_t h1 = pack_bf16(a2, a3);
    float f0 = __uint_as_float(h0 << 16);
    float f1 = __uint_as_float(h0 & 0xFFFF0000u);
    float f2 = __uint_as_float(h1 << 16);
    float f3 = __uint_as_float(h1 & 0xFFFF0000u);
    *(uint2*)&g_wd_hi[(size_t)c * D_IN + k] = make_uint2(h0, h1);
    *(uint2*)&g_wd_lo[(size_t)c * D_IN + k] =
        make_uint2(pack_bf16(a0 - f0, a1 - f1), pack_bf16(a2 - f2, a3 - f3));
}

// ============================================================================
// bf16 k16 math step, warp tile 64x64 (logits path, 8 warps)
// ============================================================================
__device__ __forceinline__ void math_kh(uint32_t cb, int kh, int wm, int wn,
                                        int j, int rr, float acc[4][8][4])
{
    uint32_t afh[4][4], afl[4][4];
    #pragma unroll
    for (int t = 0; t < 4; t++) {
        int row = wm + t * 16 + ((j & 1) << 3) + rr;
        int q = kh * 2 + (j >> 1);
        LDSM4(afh[t], sw(cb, row, q));
        LDSM4(afl[t], sw(cb + 8192, row, q));
    }
    #pragma unroll
    for (int uh = 0; uh < 2; uh++) {
        uint32_t bfh[4][2], bfl[4][2];
        #pragma unroll
        for (int up = 0; up < 2; up++) {
            int u0 = uh * 4 + up * 2;
            int nrow = wn + u0 * 8 + ((j >> 1) << 3) + rr;
            int q = kh * 2 + (j & 1);
            uint32_t t4[4];
            LDSM4(t4, sw(cb + 16384, nrow, q));
            bfh[up * 2][0] = t4[0]; bfh[up * 2][1] = t4[1];
            bfh[up * 2 + 1][0] = t4[2]; bfh[up * 2 + 1][1] = t4[3];
            LDSM4(t4, sw(cb + 32768, nrow, q));
            bfl[up * 2][0] = t4[0]; bfl[up * 2][1] = t4[1];
            bfl[up * 2 + 1][0] = t4[2]; bfl[up * 2 + 1][1] = t4[3];
        }
        #pragma unroll
        for (int t = 0; t < 4; t++)
            #pragma unroll
            for (int uu = 0; uu < 4; uu++)
                MMA_BF16(acc[t][uh * 4 + uu], afh[t], bfh[uu]);
        #pragma unroll
        for (int t = 0; t < 4; t++)
            #pragma unroll
            for (int uu = 0; uu < 4; uu++)
                MMA_BF16(acc[t][uh * 4 + uu], afh[t], bfl[uu]);
        #pragma unroll
        for (int t = 0; t < 4; t++)
            #pragma unroll
            for (int uu = 0; uu < 4; uu++)
                MMA_BF16(acc[t][uh * 4 + uu], afl[t], bfh[uu]);
    }
}

#define BUFSTRIDE 49152
#define GSMEM_TOTAL (2 * BUFSTRIDE)
#define LSTG (D_IN / 32 / LSPLIT)

__device__ __forceinline__ void cp_b_logits(uint32_t buf, int kc, int tid)
{
    size_t off = ((size_t)tid * D_IN + (size_t)kc * 32) * 2;
    const char* sh = (const char*)g_wd_hi + off;
    const char* sl = (const char*)g_wd_lo + off;
    uint32_t bh = buf + 16384, bl = buf + 32768;
    #pragma unroll
    for (int q = 0; q < 4; q++) {
        CP_ASYNC16(sw(bh, tid, q), sh + q * 16);
        CP_ASYNC16(sw(bl, tid, q), sl + q * 16);
    }
}

__device__ __forceinline__ void gen_a_logits(uint32_t buf, const float* __restrict__ x,
                                             int bm, int kc, int tid)
{
    const int ar = tid >> 1;
    const int half = tid & 1;
    float v[16];
    const float* xp = x + (size_t)(bm + ar) * D_IN + kc * 32 + half * 16;
    #pragma unroll
    for (int q = 0; q < 4; q++) {
        float4 t4 = *(const float4*)(xp + q * 4);
        v[q * 4 + 0] = t4.x; v[q * 4 + 1] = t4.y;
        v[q * 4 + 2] = t4.z; v[q * 4 + 3] = t4.w;
    }
    #pragma unroll
    for (int q2 = 0; q2 < 2; q2++) {
        uint32_t hi4[4], lo4[4];
        #pragma unroll
        for (int i = 0; i < 4; i++) {
            float f0 = v[q2 * 8 + i * 2];
            float f1 = v[q2 * 8 + i * 2 + 1];
            uint32_t hb = pack_bf16(f0, f1);
            float fh0 = __uint_as_float(hb << 16);
            float fh1 = __uint_as_float(hb & 0xFFFF0000u);
            hi4[i] = hb;
            lo4[i] = pack_bf16(f0 - fh0, f1 - fh1);
        }
        int q = half * 2 + q2;
        STS128(sw(buf, ar, q),        hi4[0], hi4[1], hi4[2], hi4[3]);
        STS128(sw(buf + 8192, ar, q), lo4[0], lo4[1], lo4[2], lo4[3]);
    }
}

__global__ __launch_bounds__(256, 1) void logits_mma(const float* __restrict__ x)
{
    extern __shared__ char smem[];
    const uint32_t sb = smem_to_u32(smem);
    const int tid = threadIdx.x;
    const int lane = tid & 31, w = tid >> 5;
    const int ks = blockIdx.x;
    const int bm = blockIdx.y * 128;
    const int wm = (w & 1) * 64, wn = (w >> 1) * 64;
    const int kc0 = ks * LSTG;

    float acc[4][8][4];
    #pragma unroll
    for (int t = 0; t < 4; t++)
        #pragma unroll
        for (int u = 0; u < 8; u++)
            #pragma unroll
            for (int c = 0; c < 4; c++) acc[t][u][c] = 0.f;

    cp_b_logits(sb, kc0, tid);
    CP_COMMIT();
    gen_a_logits(sb, x, bm, kc0, tid);
    CP_WAIT0();
    __syncthreads();

    const int j = lane >> 3, rr = lane & 7;
    for (int s = 0; s < LSTG; s++) {
        const uint32_t cb = sb + (uint32_t)(s & 1) * BUFSTRIDE;
        const uint32_t nb = sb + (uint32_t)((s + 1) & 1) * BUFSTRIDE;
        const bool has_next = (s + 1 < LSTG);
        if (has_next) { cp_b_logits(nb, kc0 + s + 1, tid); CP_COMMIT(); }
        math_kh(cb, 0, wm, wn, j, rr, acc);
        if (has_next) gen_a_logits(nb, x, bm, kc0 + s + 1, tid);
        math_kh(cb, 1, wm, wn, j, rr, acc);
        if (has_next) CP_WAIT0();
        __syncthreads();
    }

    float* lp = g_lpart + (size_t)ks * (B_DIM * 256);
    #pragma unroll
    for (int t = 0; t < 4; t++) {
        int row0 = bm + wm + t * 16 + (lane >> 2);
        #pragma unroll
        for (int u = 0; u < 8; u++) {
            int col = wn + u * 8 + (lane & 3) * 2;
            *(float2*)&lp[(size_t)row0 * 256 + col] =
                make_float2(acc[t][u][0], acc[t][u][1]);
            *(float2*)&lp[(size_t)(row0 + 8) * 256 + col] =
                make_float2(acc[t][u][2], acc[t][u][3]);
        }
    }
}

// ============================================================================
// power: sum partials + bd, softmax + warp-parallel 16x16 solve
// ============================================================================
__global__ __launch_bounds__(256) void power_kernel(const float* __restrict__ bd)
{
    const int tid = threadIdx.x;
    const int lane = tid & 31;
    const int l16 = lane & 15;
    const int b = blockIdx.x * 16 + (tid >> 4);
    const float ome = 1.f - EPSV;

    float d[16];
    {
        size_t base = (size_t)b * 256 + l16 * 16;
        #pragma unroll
        for (int q = 0; q < 4; q++) {
            float4 t0 = *(const float4*)(g_lpart + base + q * 4);
            float4 t1 = *(const float4*)(g_lpart + (size_t)1 * B_DIM * 256 + base + q * 4);
            float4 t2 = *(const float4*)(g_lpart + (size_t)2 * B_DIM * 256 + base + q * 4);
            float4 t3 = *(const float4*)(g_lpart + (size_t)3 * B_DIM * 256 + base + q * 4);
            float4 bb = *(const float4*)(bd + l16 * 16 + q * 4);
            d[q * 4 + 0] = t0.x + t1.x + t2.x + t3.x + bb.x;
            d[q * 4 + 1] = t0.y + t1.y + t2.y + t3.y + bb.y;
            d[q * 4 + 2] = t0.z + t1.z + t2.z + t3.z + bb.z;
            d[q * 4 + 3] = t0.w + t1.w + t2.w + t3.w + bb.w;
        }
        float mx = d[0];
        #pragma unroll
        for (int j = 1; j < 16; j++) mx = fmaxf(mx, d[j]);
        float s = 0.f;
        #pragma unroll
        for (int j = 0; j < 16; j++) { d[j] = expf(d[j] - mx); s += d[j]; }
        float inv = 1.f / s;
        #pragma unroll
        for (int j = 0; j < 16; j++) d[j] *= inv;
    }

    #pragma unroll
    for (int m = 1; m < 16; m <<= 1) {
        float u[16];
        #pragma unroll
        for (int i = 0; i < 16; i++)
            u[i] = __shfl_xor_sync(0xffffffffu, d[i ^ m], m);
        #pragma unroll
        for (int i = 0; i < 16; i++)
            if ((i & m) != (l16 & m)) d[i] = u[i];
    }

    float diag = 0.f;
    #pragma unroll
    for (int i = 0; i < 16; i++)
        if (i == l16) diag = d[i];

    float row[17];
    #pragma unroll
    for (int n = 0; n < 16; n++)
        row[n] = (n == l16) ? 1.f : -ome * d[n];
    row[16] = 1.f;

    #pragma unroll
    for (int p = 0; p < 16; p++) {
        float pivot = __shfl_sync(0xffffffffu, row[p], p, 16);
        float inv = 1.f / pivot;
        float f = row[p];
        #pragma unroll
        for (int c = p; c < 17; c++) {
            float pc = __shfl_sync(0xffffffffu, row[c], p, 16) * inv;
            if (l16 == p)      row[c] = pc;
            else if (l16 > p)  row[c] -= f * pc;
        }
    }

    float s = row[16];
    float z = 0.f;
    #pragma unroll
    for (int r = 15; r >= 0; r--) {
        float zr = __shfl_sync(0xffffffffu, s, r, 16);
        if (l16 == r) z = zr;
        if (l16 < r)  s -= row[r] * zr;
    }

    float zs = z;
    #pragma unroll
    for (int m = 8; m >= 1; m >>= 1)
        zs += __shfl_xor_sync(0xffffffffu, zs, m);
    float z16 = 1.f + EPSV * zs;
    float add = z16 * (1.f / 16.f) - (1.f / 16.f);
    g_power[(size_t)b * 16 + l16] = z * ome * diag + add;
}

// ============================================================================
// main_gemm: 512 threads, 16 warps (4/SMSP), warp tile 32x64, CTA 128x256.
// ============================================================================
#define NSTG 513

__device__ __forceinline__ void cp_b_512(uint32_t buf, int bn, int t, int tid)
{
    const int row = tid >> 1;
    const int q0 = (tid & 1) * 2;
    const char *sh, *sl;
    if (t < 512) {
        size_t off = ((size_t)(bn + row) * KTOT +
                      (size_t)(t & 15) * 1024 + (size_t)(t >> 4) * 32) * 2;
        sh = (const char*)g_wt_hi + off;
        sl = (const char*)g_wt_lo + off;
    } else {
        size_t off = (size_t)(bn + row) * 64;
        sh = (const char*)g_by_hi + off;
        sl = (const char*)g_by_lo + off;
    }
    uint32_t bh = buf + 16384, bl = buf + 32768;
    CP_ASYNC16(sw(bh, row, q0),     sh + q0 * 16);
    CP_ASYNC16(sw(bh, row, q0 + 1), sh + q0 * 16 + 16);
    CP_ASYNC16(sw(bl, row, q0),     sl + q0 * 16);
    CP_ASYNC16(sw(bl, row, q0 + 1), sl + q0 * 16 + 16);
}

// A tile gen: thread handles row ar = tid>>2, 8 k values at granule sub = tid&3
__device__ __forceinline__ void gen_a_512(uint32_t buf, int bm, int t, int tid,
                                          const float* xv /*8 cached values*/)
{
    const int ar = tid >> 2;
    const int sub = tid & 3;
    float v[8];
    float p;
    if (t < 512) {
        const int n = t & 15;
        p = g_power[(size_t)(bm + ar) * 16 + n];
        #pragma unroll
        for (int i = 0; i < 8; i++) v[i] = xv[i];
    } else {
        p = 1.f;
        if (sub < 2) {
            const float* pp = &g_power[(size_t)(bm + ar) * 16 + sub * 8];
            float4 a = *(const float4*)pp;
            float4 b = *(const float4*)(pp + 4);
            v[0] = a.x; v[1] = a.y; v[2] = a.z; v[3] = a.w;
            v[4] = b.x; v[5] = b.y; v[6] = b.z; v[7] = b.w;
        } else {
            #pragma unroll
            for (int i = 0; i < 8; i++) v[i] = 0.f;
        }
    }
    uint32_t hi4[4], lo4[4];
    #pragma unroll
    for (int i = 0; i < 4; i++) {
        float f0 = v[i * 2]     * p;
        float f1 = v[i * 2 + 1] * p;
        uint32_t hb = pack_bf16(f0, f1);
        float fh0 = __uint_as_float(hb << 16);
        float fh1 = __uint_as_float(hb & 0xFFFF0000u);
        hi4[i] = hb;
        lo4[i] = pack_bf16(f0 - fh0, f1 - fh1);
    }
    STS128(sw(buf, ar, sub),        hi4[0], hi4[1], hi4[2], hi4[3]);
    STS128(sw(buf + 8192, ar, sub), lo4[0], lo4[1], lo4[2], lo4[3]);
}

// one k16 math step, warp tile 32x64
__device__ __forceinline__ void math_kh32(uint32_t cb, int kh, int wm, int wn,
                                          int j, int rr, float acc[2][8][4])
{
    uint32_t afh[2][4], afl[2][4];
    #pragma unroll
    for (int t = 0; t < 2; t++) {
        int row = wm + t * 16 + ((j & 1) << 3) + rr;
        int q = kh * 2 + (j >> 1);
        LDSM4(afh[t], sw(cb, row, q));
        LDSM4(afl[t], sw(cb + 8192, row, q));
    }
    #pragma unroll
    for (int uh = 0; uh < 2; uh++) {
        uint32_t bfh[4][2], bfl[4][2];
        #pragma unroll
        for (int up = 0; up < 2; up++) {
            int u0 = uh * 4 + up * 2;
            int nrow = wn + u0 * 8 + ((j >> 1) << 3) + rr;
            int q = kh * 2 + (j & 1);
            uint32_t t4[4];
            LDSM4(t4, sw(cb + 16384, nrow, q));
            bfh[up * 2][0] = t4[0]; bfh[up * 2][1] = t4[1];
            bfh[up * 2 + 1][0] = t4[2]; bfh[up * 2 + 1][1] = t4[3];
            LDSM4(t4, sw(cb + 32768, nrow, q));
            bfl[up * 2][0] = t4[0]; bfl[up * 2][1] = t4[1];
            bfl[up * 2 + 1][0] = t4[2]; bfl[up * 2 + 1][1] = t4[3];
        }
        #pragma unroll
        for (int t = 0; t < 2; t++)
            #pragma unroll
            for (int uu = 0; uu < 4; uu++)
                MMA_BF16(acc[t][uh * 4 + uu], afh[t], bfh[uu]);
        #pragma unroll
        for (int t = 0; t < 2; t++)
            #pragma unroll
            for (int uu = 0; uu < 4; uu++)
                MMA_BF16(acc[t][uh * 4 + uu], afh[t], bfl[uu]);
        #pragma unroll
        for (int t = 0; t < 2; t++)
            #pragma unroll
            for (int uu = 0; uu < 4; uu++)
                MMA_BF16(acc[t][uh * 4 + uu], afl[t], bfh[uu]);
    }
}

__global__ __launch_bounds__(512, 1) void main_gemm(
    const float* __restrict__ x, float* __restrict__ out)
{
    extern __shared__ char smem[];
    const uint32_t sb = smem_to_u32(smem);
    const int tid = threadIdx.x;
    const int lane = tid & 31, w = tid >> 5;
    const int bm = blockIdx.y * 128;
    const int bn = blockIdx.x * 256;
    const int wm = (w & 3) * 32, wn = (w >> 2) * 64;

    float acc[2][8][4];
    #pragma unroll
    for (int t = 0; t < 2; t++)
        #pragma unroll
        for (int u = 0; u < 8; u++)
            #pragma unroll
            for (int c = 0; c < 4; c++) acc[t][u][c] = 0.f;

    // x window cache: thread's 8 floats for the current o-chunk
    const int ar = tid >> 2;
    const float* xbase = x + (size_t)(bm + ar) * D_IN + (tid & 3) * 8;
    float xv[8];
    {
        float4 a = *(const float4*)xbase;
        float4 b = *(const float4*)(xbase + 4);
        xv[0]=a.x; xv[1]=a.y; xv[2]=a.z; xv[3]=a.w;
        xv[4]=b.x; xv[5]=b.y; xv[6]=b.z; xv[7]=b.w;
    }

    cp_b_512(sb, bn, 0, tid);
    CP_COMMIT();
    gen_a_512(sb, bm, 0, tid, xv);
    CP_WAIT0();
    __syncthreads();

    const int j = lane >> 3, rr = lane & 7;

    for (int s = 0; s < NSTG; s++) {
        const uint32_t cb = sb + (uint32_t)(s & 1) * BUFSTRIDE;
        const uint32_t nb = sb + (uint32_t)((s + 1) & 1) * BUFSTRIDE;
        const bool has_next = (s + 1 < NSTG);

        if (has_next) {
            cp_b_512(nb, bn, s + 1, tid);
            CP_COMMIT();
        }
        math_kh32(cb, 0, wm, wn, j, rr, acc);
        if (has_next) {
            const int t = s + 1;
            if ((t & 15) == 0 && t < 512) {   // new o-chunk: refresh x cache
                const float* xp = xbase + (t >> 4) * 32;
                float4 a = *(const float4*)xp;
                float4 b = *(const float4*)(xp + 4);
                xv[0]=a.x; xv[1]=a.y; xv[2]=a.z; xv[3]=a.w;
                xv[4]=b.x; xv[5]=b.y; xv[6]=b.z; xv[7]=b.w;
            }
            gen_a_512(nb, bm, t, tid, xv);
        }
        math_kh32(cb, 1, wm, wn, j, rr, acc);
        if (has_next) CP_WAIT0();
        __syncthreads();
    }

    #pragma unroll
    for (int t = 0; t < 2; t++) {
        int row0 = bm + wm + t * 16 + (lane >> 2);
        #pragma unroll
        for (int u = 0; u < 8; u++) {
            int col = bn + wn + u * 8 + (lane & 3) * 2;
            *(float2*)&out[(size_t)row0 * D_OUT + col] =
                make_float2(acc[t][u][0], acc[t][u][1]);
            *(float2*)&out[(size_t)(row0 + 8) * D_OUT + col] =
                make_float2(acc[t][u][2], acc[t][u][3]);
        }
    }
}

// ============================================================================
extern "C" void kernel_launch(void* const* d_in, const int* in_sizes, int n_in,
                              void* d_out, int out_size)
{
    const float* x  = (const float*)d_in[0];
    const float* Wy = (const float*)d_in[1];
    const float* by = (const float*)d_in[2];
    const float* Wd = (const float*)d_in[3];
    const float* bd = (const float*)d_in[4];
    float* out = (float*)d_out;

    cudaFuncSetAttribute(main_gemm, cudaFuncAttributeMaxDynamicSharedMemorySize,
                         GSMEM_TOTAL);
    cudaFuncSetAttribute(logits_mma, cudaFuncAttributeMaxDynamicSharedMemorySize,
                         GSMEM_TOTAL);

    transpose_split<<<dim3(KTOT / 64, D_OUT / 64), 256>>>(Wy);
    by_prep<<<D_OUT / 256, 256>>>(by);
    wd_prep<<<256, 256>>>(Wd);
    logits_mma<<<dim3(LSPLIT, B_DIM / 128), 256, GSMEM_TOTAL>>>(x);
    power_kernel<<<B_DIM / 16, 256>>>(bd);
    main_gemm<<<dim3(D_OUT / 256, B_DIM / 128), 512, GSMEM_TOTAL>>>(x, out);
}

// round 13
// speedup vs baseline: 4.3523x; 1.5242x over previous
#include <cuda_runtime.h>
#include <cuda_bf16.h>
#include <cuda_fp16.h>
#include <cstdint>

#define B_DIM 4096
#define N_CIT 16
#define D_IN  1024
#define D_OUT 1024
#define KTOT  (N_CIT * D_IN)
#define EPSV  0.01f
#define LSPLIT 4

__device__ float g_lpart[LSPLIT * B_DIM * 256];
__device__ float g_power [B_DIM * 16];
__device__ __half g_wf16[(size_t)D_OUT * KTOT];   // [o][k] K-major, fp16 single plane
__device__ __half g_byf16[(size_t)D_OUT * 32];    // [o][k] k 0..15 real, rest 0
__device__ __nv_bfloat16 g_wd_hi[256 * D_IN];
__device__ __nv_bfloat16 g_wd_lo[256 * D_IN];

__device__ __forceinline__ uint32_t smem_to_u32(const void* p) {
    uint32_t a;
    asm("{ .reg .u64 t; cvta.to.shared.u64 t, %1; cvt.u32.u64 %0, t; }" : "=r"(a) : "l"(p));
    return a;
}
__device__ __forceinline__ uint32_t sw(uint32_t base, int row, int q) {
    return base + row * 64 + (((uint32_t)(q ^ ((row >> 1) & 3))) << 4);
}
__device__ __forceinline__ uint32_t pack_bf16(float f0, float f1) {
    uint32_t r;
    asm("cvt.rn.bf16x2.f32 %0, %1, %2;" : "=r"(r) : "f"(f1), "f"(f0));
    return r;
}
__device__ __forceinline__ uint32_t pack_f16(__half h0, __half h1) {
    __half2 h = __halves2half2(h0, h1);
    return *(uint32_t*)&h;
}
#define CP_ASYNC16(dst, src) \
    asm volatile("cp.async.cg.shared.global [%0], [%1], 16;" :: "r"(dst), "l"(src) : "memory")
#define CP_COMMIT() asm volatile("cp.async.commit_group;" ::: "memory")
#define CP_WAIT0()  asm volatile("cp.async.wait_group 0;" ::: "memory")
#define LDSM4(r, addr) \
    asm volatile("ldmatrix.sync.aligned.m8n8.x4.shared.b16 {%0,%1,%2,%3}, [%4];" \
        : "=r"((r)[0]), "=r"((r)[1]), "=r"((r)[2]), "=r"((r)[3]) : "r"(addr))
#define MMA_BF16(d, a, b) \
    asm volatile("mma.sync.aligned.m16n8k16.row.col.f32.bf16.bf16.f32 " \
        "{%0,%1,%2,%3}, {%4,%5,%6,%7}, {%8,%9}, {%0,%1,%2,%3};" \
        : "+f"((d)[0]), "+f"((d)[1]), "+f"((d)[2]), "+f"((d)[3]) \
        : "r"((a)[0]), "r"((a)[1]), "r"((a)[2]), "r"((a)[3]), "r"((b)[0]), "r"((b)[1]))
#define MMA_F16(d, a, b) \
    asm volatile("mma.sync.aligned.m16n8k16.row.col.f32.f16.f16.f32 " \
        "{%0,%1,%2,%3}, {%4,%5,%6,%7}, {%8,%9}, {%0,%1,%2,%3};" \
        : "+f"((d)[0]), "+f"((d)[1]), "+f"((d)[2]), "+f"((d)[3]) \
        : "r"((a)[0]), "r"((a)[1]), "r"((a)[2]), "r"((a)[3]), "r"((b)[0]), "r"((b)[1]))
#define STS128(addr, r0, r1, r2, r3) \
    asm volatile("st.shared.v4.b32 [%0], {%1,%2,%3,%4};" \
        :: "r"(addr), "r"(r0), "r"(r1), "r"(r2), "r"(r3) : "memory")

// ============================================================================
// Kernel 0a: transpose + fp16 round: Wy[16384,1024] -> g_wf16[1024][16384]
// ============================================================================
__global__ __launch_bounds__(256) void transpose_f16(const float* __restrict__ Wy)
{
    __shared__ float T[64][65];
    const int k0 = blockIdx.x * 64;
    const int o0 = blockIdx.y * 64;
    const int tid = threadIdx.x;
    {
        int kr = tid >> 4, o4 = tid & 15;
        #pragma unroll
        for (int r = 0; r < 4; r++) {
            int k = kr + r * 16;
            float4 v = *(const float4*)&Wy[(size_t)(k0 + k) * D_OUT + o0 + o4 * 4];
            T[k][o4 * 4 + 0] = v.x;  T[k][o4 * 4 + 1] = v.y;
            T[k][o4 * 4 + 2] = v.z;  T[k][o4 * 4 + 3] = v.w;
        }
    }
    __syncthreads();
    {
        int o = tid >> 2, kq = tid & 3;
        uint32_t hv[8];
        #pragma unroll
        for (int i = 0; i < 8; i++)
            hv[i] = pack_f16(__float2half_rn(T[kq * 16 + i * 2][o]),
                             __float2half_rn(T[kq * 16 + i * 2 + 1][o]));
        size_t dst = (size_t)(o0 + o) * KTOT + k0 + kq * 16;
        *(uint4*)&g_wf16[dst]     = make_uint4(hv[0], hv[1], hv[2], hv[3]);
        *(uint4*)&g_wf16[dst + 8] = make_uint4(hv[4], hv[5], hv[6], hv[7]);
    }
}

// ============================================================================
// Kernel 0b: by[16][1024] -> g_byf16[1024][32] fp16 (k 16..31 zero)
// ============================================================================
__global__ __launch_bounds__(256) void by_prep(const float* __restrict__ by)
{
    int o = blockIdx.x * 256 + threadIdx.x;
    if (o >= D_OUT) return;
    #pragma unroll
    for (int kp = 0; kp < 8; kp++) {
        *(uint32_t*)&g_byf16[(size_t)o * 32 + kp * 2] =
            pack_f16(__float2half_rn(by[(size_t)(kp * 2) * D_OUT + o]),
                     __float2half_rn(by[(size_t)(kp * 2 + 1) * D_OUT + o]));
    }
    #pragma unroll
    for (int kp = 8; kp < 16; kp++)
        *(uint32_t*)&g_byf16[(size_t)o * 32 + kp * 2] = 0u;
}

// ============================================================================
// Kernel 0c: Wd -> g_wd (K-major, bf16 hi/lo) — logits path
// ============================================================================
__global__ __launch_bounds__(256) void wd_prep(const float* __restrict__ Wd)
{
    const int c = blockIdx.x;
    const int n = c >> 4, j = c & 15;
    const int tid = threadIdx.x;
    const float* src = Wd + (size_t)n * (D_IN * 16) + j;
    int k = tid * 4;
    float a0 = src[(size_t)(k + 0) * 16];
    float a1 = src[(size_t)(k + 1) * 16];
    float a2 = src[(size_t)(k + 2) * 16];
    float a3 = src[(size_t)(k + 3) * 16];
    uint32_t h0 = pack_bf16(a0, a1);
    uint32_t h1 = pack_bf16(a2, a3);
    float f0 = __uint_as_float(h0 << 16);
    float f1 = __uint_as_float(h0 & 0xFFFF0000u);
    float f2 = __uint_as_float(h1 << 16);
    float f3 = __uint_as_float(h1 & 0xFFFF0000u);
    *(uint2*)&g_wd_hi[(size_t)c * D_IN + k] = make_uint2(h0, h1);
    *(uint2*)&g_wd_lo[(size_t)c * D_IN + k] =
        make_uint2(pack_bf16(a0 - f0, a1 - f1), pack_bf16(a2 - f2, a3 - f3));
}

// ============================================================================
// logits path (split-bf16, unchanged from best)
// ============================================================================
__device__ __forceinline__ void math_kh(uint32_t cb, int kh, int wm, int wn,
                                        int j, int rr, float acc[4][8][4])
{
    uint32_t afh[4][4], afl[4][4];
    #pragma unroll
    for (int t = 0; t < 4; t++) {
        int row = wm + t * 16 + ((j & 1) << 3) + rr;
        int q = kh * 2 + (j >> 1);
        LDSM4(afh[t], sw(cb, row, q));
        LDSM4(afl[t], sw(cb + 8192, row, q));
    }
    #pragma unroll
    for (int uh = 0; uh < 2; uh++) {
        uint32_t bfh[4][2], bfl[4][2];
        #pragma unroll
        for (int up = 0; up < 2; up++) {
            int u0 = uh * 4 + up * 2;
            int nrow = wn + u0 * 8 + ((j >> 1) << 3) + rr;
            int q = kh * 2 + (j & 1);
            uint32_t t4[4];
            LDSM4(t4, sw(cb + 16384, nrow, q));
            bfh[up * 2][0] = t4[0]; bfh[up * 2][1] = t4[1];
            bfh[up * 2 + 1][0] = t4[2]; bfh[up * 2 + 1][1] = t4[3];
            LDSM4(t4, sw(cb + 32768, nrow, q));
            bfl[up * 2][0] = t4[0]; bfl[up * 2][1] = t4[1];
            bfl[up * 2 + 1][0] = t4[2]; bfl[up * 2 + 1][1] = t4[3];
        }
        #pragma unroll
        for (int t = 0; t < 4; t++)
            #pragma unroll
            for (int uu = 0; uu < 4; uu++)
                MMA_BF16(acc[t][uh * 4 + uu], afh[t], bfh[uu]);
        #pragma unroll
        for (int t = 0; t < 4; t++)
            #pragma unroll
            for (int uu = 0; uu < 4; uu++)
                MMA_BF16(acc[t][uh * 4 + uu], afh[t], bfl[uu]);
        #pragma unroll
        for (int t = 0; t < 4; t++)
            #pragma unroll
            for (int uu = 0; uu < 4; uu++)
                MMA_BF16(acc[t][uh * 4 + uu], afl[t], bfh[uu]);
    }
}

#define LBUFSTRIDE 49152
#define LSMEM_TOTAL (2 * LBUFSTRIDE)
#define LSTG (D_IN / 32 / LSPLIT)

__device__ __forceinline__ void cp_b_logits(uint32_t buf, int kc, int tid)
{
    size_t off = ((size_t)tid * D_IN + (size_t)kc * 32) * 2;
    const char* sh = (const char*)g_wd_hi + off;
    const char* sl = (const char*)g_wd_lo + off;
    uint32_t bh = buf + 16384, bl = buf + 32768;
    #pragma unroll
    for (int q = 0; q < 4; q++) {
        CP_ASYNC16(sw(bh, tid, q), sh + q * 16);
        CP_ASYNC16(sw(bl, tid, q), sl + q * 16);
    }
}

__device__ __forceinline__ void gen_a_logits(uint32_t buf, const float* __restrict__ x,
                                             int bm, int kc, int tid)
{
    const int ar = tid >> 1;
    const int half = tid & 1;
    float v[16];
    const float* xp = x + (size_t)(bm + ar) * D_IN + kc * 32 + half * 16;
    #pragma unroll
    for (int q = 0; q < 4; q++) {
        float4 t4 = *(const float4*)(xp + q * 4);
        v[q * 4 + 0] = t4.x; v[q * 4 + 1] = t4.y;
        v[q * 4 + 2] = t4.z; v[q * 4 + 3] = t4.w;
    }
    #pragma unroll
    for (int q2 = 0; q2 < 2; q2++) {
        uint32_t hi4[4], lo4[4];
        #pragma unroll
        for (int i = 0; i < 4; i++) {
            float f0 = v[q2 * 8 + i * 2];
            float f1 = v[q2 * 8 + i * 2 + 1];
            uint32_t hb = pack_bf16(f0, f1);
            float fh0 = __uint_as_float(hb << 16);
            float fh1 = __uint_as_float(hb & 0xFFFF0000u);
            hi4[i] = hb;
            lo4[i] = pack_bf16(f0 - fh0, f1 - fh1);
        }
        int q = half * 2 + q2;
        STS128(sw(buf, ar, q),        hi4[0], hi4[1], hi4[2], hi4[3]);
        STS128(sw(buf + 8192, ar, q), lo4[0], lo4[1], lo4[2], lo4[3]);
    }
}

__global__ __launch_bounds__(256, 1) void logits_mma(const float* __restrict__ x)
{
    extern __shared__ char smem[];
    const uint32_t sb = smem_to_u32(smem);
    const int tid = threadIdx.x;
    const int lane = tid & 31, w = tid >> 5;
    const int ks = blockIdx.x;
    const int bm = blockIdx.y * 128;
    const int wm = (w & 1) * 64, wn = (w >> 1) * 64;
    const int kc0 = ks * LSTG;

    float acc[4][8][4];
    #pragma unroll
    for (int t = 0; t < 4; t++)
        #pragma unroll
        for (int u = 0; u < 8; u++)
            #pragma unroll
            for (int c = 0; c < 4; c++) acc[t][u][c] = 0.f;

    cp_b_logits(sb, kc0, tid);
    CP_COMMIT();
    gen_a_logits(sb, x, bm, kc0, tid);
    CP_WAIT0();
    __syncthreads();

    const int j = lane >> 3, rr = lane & 7;
    for (int s = 0; s < LSTG; s++) {
        const uint32_t cb = sb + (uint32_t)(s & 1) * LBUFSTRIDE;
        const uint32_t nb = sb + (uint32_t)((s + 1) & 1) * LBUFSTRIDE;
        const bool has_next = (s + 1 < LSTG);
        if (has_next) { cp_b_logits(nb, kc0 + s + 1, tid); CP_COMMIT(); }
        math_kh(cb, 0, wm, wn, j, rr, acc);
        if (has_next) gen_a_logits(nb, x, bm, kc0 + s + 1, tid);
        math_kh(cb, 1, wm, wn, j, rr, acc);
        if (has_next) CP_WAIT0();
        __syncthreads();
    }

    float* lp = g_lpart + (size_t)ks * (B_DIM * 256);
    #pragma unroll
    for (int t = 0; t < 4; t++) {
        int row0 = bm + wm + t * 16 + (lane >> 2);
        #pragma unroll
        for (int u = 0; u < 8; u++) {
            int col = wn + u * 8 + (lane & 3) * 2;
            *(float2*)&lp[(size_t)row0 * 256 + col] =
                make_float2(acc[t][u][0], acc[t][u][1]);
            *(float2*)&lp[(size_t)(row0 + 8) * 256 + col] =
                make_float2(acc[t][u][2], acc[t][u][3]);
        }
    }
}

// ============================================================================
// power: sum partials + bd, softmax + warp-parallel 16x16 solve
// ============================================================================
__global__ __launch_bounds__(256) void power_kernel(const float* __restrict__ bd)
{
    const int tid = threadIdx.x;
    const int lane = tid & 31;
    const int l16 = lane & 15;
    const int b = blockIdx.x * 16 + (tid >> 4);
    const float ome = 1.f - EPSV;

    float d[16];
    {
        size_t base = (size_t)b * 256 + l16 * 16;
        #pragma unroll
        for (int q = 0; q < 4; q++) {
            float4 t0 = *(const float4*)(g_lpart + base + q * 4);
            float4 t1 = *(const float4*)(g_lpart + (size_t)1 * B_DIM * 256 + base + q * 4);
            float4 t2 = *(const float4*)(g_lpart + (size_t)2 * B_DIM * 256 + base + q * 4);
            float4 t3 = *(const float4*)(g_lpart + (size_t)3 * B_DIM * 256 + base + q * 4);
            float4 bb = *(const float4*)(bd + l16 * 16 + q * 4);
            d[q * 4 + 0] = t0.x + t1.x + t2.x + t3.x + bb.x;
            d[q * 4 + 1] = t0.y + t1.y + t2.y + t3.y + bb.y;
            d[q * 4 + 2] = t0.z + t1.z + t2.z + t3.z + bb.z;
            d[q * 4 + 3] = t0.w + t1.w + t2.w + t3.w + bb.w;
        }
        float mx = d[0];
        #pragma unroll
        for (int j = 1; j < 16; j++) mx = fmaxf(mx, d[j]);
        float s = 0.f;
        #pragma unroll
        for (int j = 0; j < 16; j++) { d[j] = expf(d[j] - mx); s += d[j]; }
        float inv = 1.f / s;
        #pragma unroll
        for (int j = 0; j < 16; j++) d[j] *= inv;
    }

    #pragma unroll
    for (int m = 1; m < 16; m <<= 1) {
        float u[16];
        #pragma unroll
        for (int i = 0; i < 16; i++)
            u[i] = __shfl_xor_sync(0xffffffffu, d[i ^ m], m);
        #pragma unroll
        for (int i = 0; i < 16; i++)
            if ((i & m) != (l16 & m)) d[i] = u[i];
    }

    float diag = 0.f;
    #pragma unroll
    for (int i = 0; i < 16; i++)
        if (i == l16) diag = d[i];

    float row[17];
    #pragma unroll
    for (int n = 0; n < 16; n++)
        row[n] = (n == l16) ? 1.f : -ome * d[n];
    row[16] = 1.f;

    #pragma unroll
    for (int p = 0; p < 16; p++) {
        float pivot = __shfl_sync(0xffffffffu, row[p], p, 16);
        float inv = 1.f / pivot;
        float f = row[p];
        #pragma unroll
        for (int c = p; c < 17; c++) {
            float pc = __shfl_sync(0xffffffffu, row[c], p, 16) * inv;
            if (l16 == p)      row[c] = pc;
            else if (l16 > p)  row[c] -= f * pc;
        }
    }

    float s = row[16];
    float z = 0.f;
    #pragma unroll
    for (int r = 15; r >= 0; r--) {
        float zr = __shfl_sync(0xffffffffu, s, r, 16);
        if (l16 == r) z = zr;
        if (l16 < r)  s -= row[r] * zr;
    }

    float zs = z;
    #pragma unroll
    for (int m = 8; m >= 1; m >>= 1)
        zs += __shfl_xor_sync(0xffffffffu, zs, m);
    float z16 = 1.f + EPSV * zs;
    float add = z16 * (1.f / 16.f) - (1.f / 16.f);
    g_power[(size_t)b * 16 + l16] = z * ome * diag + add;
}

// ============================================================================
// main_gemm: fp16 2-pass, exact split-A (16x scaled), single-plane B.
// 512 threads, 16 warps, warp tile 32x64, CTA 128x256, K-chunk 32.
// Buffer (32KB): A_hi[8K] A_lo[8K] B[16K]
// ============================================================================
#define MBUFSTRIDE 32768
#define MSMEM_TOTAL (2 * MBUFSTRIDE)
#define NSTG 513

__device__ __forceinline__ void cp_b_main(uint32_t buf, int bn, int t, int tid)
{
    const int row = tid >> 1;
    const int q0 = (tid & 1) * 2;
    const char* sh;
    if (t < 512) {
        size_t off = ((size_t)(bn + row) * KTOT +
                      (size_t)(t & 15) * 1024 + (size_t)(t >> 4) * 32) * 2;
        sh = (const char*)g_wf16 + off;
    } else {
        sh = (const char*)g_byf16 + (size_t)(bn + row) * 64;
    }
    uint32_t bb = buf + 16384;
    CP_ASYNC16(sw(bb, row, q0),     sh + q0 * 16);
    CP_ASYNC16(sw(bb, row, q0 + 1), sh + q0 * 16 + 16);
}

// A gen: a = 16*p*x split exactly into fp16 hi + lo. Thread: row tid>>2, granule tid&3.
__device__ __forceinline__ void gen_a_main(uint32_t buf, int bm, int t, int tid,
                                           const float* xv)
{
    const int ar = tid >> 2;
    const int sub = tid & 3;
    float v[8];
    float p;
    if (t < 512) {
        const int n = t & 15;
        p = 16.f * g_power[(size_t)(bm + ar) * 16 + n];
        #pragma unroll
        for (int i = 0; i < 8; i++) v[i] = xv[i];
    } else {
        p = 16.f;
        if (sub < 2) {
            const float* pp = &g_power[(size_t)(bm + ar) * 16 + sub * 8];
            float4 a = *(const float4*)pp;
            float4 b = *(const float4*)(pp + 4);
            v[0] = a.x; v[1] = a.y; v[2] = a.z; v[3] = a.w;
            v[4] = b.x; v[5] = b.y; v[6] = b.z; v[7] = b.w;
        } else {
            #pragma unroll
            for (int i = 0; i < 8; i++) v[i] = 0.f;
        }
    }
    uint32_t hi4[4], lo4[4];
    #pragma unroll
    for (int i = 0; i < 4; i++) {
        float f0 = v[i * 2]     * p;
        float f1 = v[i * 2 + 1] * p;
        __half h0 = __float2half_rn(f0);
        __half h1 = __float2half_rn(f1);
        hi4[i] = pack_f16(h0, h1);
        lo4[i] = pack_f16(__float2half_rn(f0 - __half2float(h0)),
                          __float2half_rn(f1 - __half2float(h1)));
    }
    STS128(sw(buf, ar, sub),        hi4[0], hi4[1], hi4[2], hi4[3]);
    STS128(sw(buf + 8192, ar, sub), lo4[0], lo4[1], lo4[2], lo4[3]);
}

// one k16 math step, warp tile 32x64, 2 fp16 passes over single-plane B
__device__ __forceinline__ void math_f16(uint32_t cb, int kh, int wm, int wn,
                                         int j, int rr, float acc[2][8][4])
{
    uint32_t afh[2][4], afl[2][4];
    #pragma unroll
    for (int t = 0; t < 2; t++) {
        int row = wm + t * 16 + ((j & 1) << 3) + rr;
        int q = kh * 2 + (j >> 1);
        LDSM4(afh[t], sw(cb, row, q));
        LDSM4(afl[t], sw(cb + 8192, row, q));
    }
    #pragma unroll
    for (int uh = 0; uh < 2; uh++) {
        uint32_t bf[4][2];
        #pragma unroll
        for (int up = 0; up < 2; up++) {
            int u0 = uh * 4 + up * 2;
            int nrow = wn + u0 * 8 + ((j >> 1) << 3) + rr;
            int q = kh * 2 + (j & 1);
            uint32_t t4[4];
            LDSM4(t4, sw(cb + 16384, nrow, q));
            bf[up * 2][0] = t4[0]; bf[up * 2][1] = t4[1];
            bf[up * 2 + 1][0] = t4[2]; bf[up * 2 + 1][1] = t4[3];
        }
        #pragma unroll
        for (int t = 0; t < 2; t++)
            #pragma unroll
            for (int uu = 0; uu < 4; uu++)
                MMA_F16(acc[t][uh * 4 + uu], afh[t], bf[uu]);
        #pragma unroll
        for (int t = 0; t < 2; t++)
            #pragma unroll
            for (int uu = 0; uu < 4; uu++)
                MMA_F16(acc[t][uh * 4 + uu], afl[t], bf[uu]);
    }
}

__global__ __launch_bounds__(512, 1) void main_gemm(
    const float* __restrict__ x, float* __restrict__ out)
{
    extern __shared__ char smem[];
    const uint32_t sb = smem_to_u32(smem);
    const int tid = threadIdx.x;
    const int lane = tid & 31, w = tid >> 5;
    const int bm = blockIdx.y * 128;
    const int bn = blockIdx.x * 256;
    const int wm = (w & 3) * 32, wn = (w >> 2) * 64;

    float acc[2][8][4];
    #pragma unroll
    for (int t = 0; t < 2; t++)
        #pragma unroll
        for (int u = 0; u < 8; u++)
            #pragma unroll
            for (int c = 0; c < 4; c++) acc[t][u][c] = 0.f;

    const int ar = tid >> 2;
    const float* xbase = x + (size_t)(bm + ar) * D_IN + (tid & 3) * 8;
    float xv[8];
    {
        float4 a = *(const float4*)xbase;
        float4 b = *(const float4*)(xbase + 4);
        xv[0]=a.x; xv[1]=a.y; xv[2]=a.z; xv[3]=a.w;
        xv[4]=b.x; xv[5]=b.y; xv[6]=b.z; xv[7]=b.w;
    }

    cp_b_main(sb, bn, 0, tid);
    CP_COMMIT();
    gen_a_main(sb, bm, 0, tid, xv);
    CP_WAIT0();
    __syncthreads();

    const int j = lane >> 3, rr = lane & 7;

    for (int s = 0; s < NSTG; s++) {
        const uint32_t cb = sb + (uint32_t)(s & 1) * MBUFSTRIDE;
        const uint32_t nb = sb + (uint32_t)((s + 1) & 1) * MBUFSTRIDE;
        const bool has_next = (s + 1 < NSTG);

        if (has_next) {
            cp_b_main(nb, bn, s + 1, tid);
            CP_COMMIT();
        }
        math_f16(cb, 0, wm, wn, j, rr, acc);
        if (has_next) {
            const int t = s + 1;
            if ((t & 15) == 0 && t < 512) {
                const float* xp = xbase + (t >> 4) * 32;
                float4 a = *(const float4*)xp;
                float4 b = *(const float4*)(xp + 4);
                xv[0]=a.x; xv[1]=a.y; xv[2]=a.z; xv[3]=a.w;
                xv[4]=b.x; xv[5]=b.y; xv[6]=b.z; xv[7]=b.w;
            }
            gen_a_main(nb, bm, t, tid, xv);
        }
        math_f16(cb, 1, wm, wn, j, rr, acc);
        if (has_next) CP_WAIT0();
        __syncthreads();
    }

    const float sc = 1.f / 16.f;
    #pragma unroll
    for (int t = 0; t < 2; t++) {
        int row0 = bm + wm + t * 16 + (lane >> 2);
        #pragma unroll
        for (int u = 0; u < 8; u++) {
            int col = bn + wn + u * 8 + (lane & 3) * 2;
            *(float2*)&out[(size_t)row0 * D_OUT + col] =
                make_float2(acc[t][u][0] * sc, acc[t][u][1] * sc);
            *(float2*)&out[(size_t)(row0 + 8) * D_OUT + col] =
                make_float2(acc[t][u][2] * sc, acc[t][u][3] * sc);
        }
    }
}

// ============================================================================
extern "C" void kernel_launch(void* const* d_in, const int* in_sizes, int n_in,
                              void* d_out, int out_size)
{
    const float* x  = (const float*)d_in[0];
    const float* Wy = (const float*)d_in[1];
    const float* by = (const float*)d_in[2];
    const float* Wd = (const float*)d_in[3];
    const float* bd = (const float*)d_in[4];
    float* out = (float*)d_out;

    cudaFuncSetAttribute(main_gemm, cudaFuncAttributeMaxDynamicSharedMemorySize,
                         MSMEM_TOTAL);
    cudaFuncSetAttribute(logits_mma, cudaFuncAttributeMaxDynamicSharedMemorySize,
                         LSMEM_TOTAL);

    transpose_f16<<<dim3(KTOT / 64, D_OUT / 64), 256>>>(Wy);
    by_prep<<<D_OUT / 256, 256>>>(by);
    wd_prep<<<256, 256>>>(Wd);
    logits_mma<<<dim3(LSPLIT, B_DIM / 128), 256, LSMEM_TOTAL>>>(x);
    power_kernel<<<B_DIM / 16, 256>>>(bd);
    main_gemm<<<dim3(D_OUT / 256, B_DIM / 128), 512, MSMEM_TOTAL>>>(x, out);
}

// round 14
// speedup vs baseline: 6.9108x; 1.5878x over previous
#include <cuda_runtime.h>
#include <cuda_bf16.h>
#include <cuda_fp16.h>
#include <cstdint>

#define B_DIM 4096
#define N_CIT 16
#define D_IN  1024
#define D_OUT 1024
#define KTOT  (N_CIT * D_IN)
#define EPSV  0.01f
#define LSPLIT 4

__device__ float g_lpart[LSPLIT * B_DIM * 256];
__device__ float g_power [B_DIM * 16];
__device__ __half g_wf16[(size_t)D_OUT * KTOT];   // [o][k] K-major, fp16 single plane
__device__ __half g_byf16[(size_t)D_OUT * 32];    // [o][k] k 0..15 real, rest 0
__device__ __nv_bfloat16 g_wd_hi[256 * D_IN];
__device__ __nv_bfloat16 g_wd_lo[256 * D_IN];

__device__ __forceinline__ uint32_t smem_to_u32(const void* p) {
    uint32_t a;
    asm("{ .reg .u64 t; cvta.to.shared.u64 t, %1; cvt.u32.u64 %0, t; }" : "=r"(a) : "l"(p));
    return a;
}
__device__ __forceinline__ uint32_t sw(uint32_t base, int row, int q) {
    return base + row * 64 + (((uint32_t)(q ^ ((row >> 1) & 3))) << 4);
}
__device__ __forceinline__ uint32_t pack_bf16(float f0, float f1) {
    uint32_t r;
    asm("cvt.rn.bf16x2.f32 %0, %1, %2;" : "=r"(r) : "f"(f1), "f"(f0));
    return r;
}
__device__ __forceinline__ uint32_t pack_f16(__half h0, __half h1) {
    __half2 h = __halves2half2(h0, h1);
    return *(uint32_t*)&h;
}
__device__ __forceinline__ uint32_t pack_f16f(float f0, float f1) {
    uint32_t r;
    asm("cvt.rn.f16x2.f32 %0, %1, %2;" : "=r"(r) : "f"(f1), "f"(f0));
    return r;
}
#define CP_ASYNC16(dst, src) \
    asm volatile("cp.async.cg.shared.global [%0], [%1], 16;" :: "r"(dst), "l"(src) : "memory")
#define CP_COMMIT() asm volatile("cp.async.commit_group;" ::: "memory")
#define CP_WAIT0()  asm volatile("cp.async.wait_group 0;" ::: "memory")
#define LDSM4(r, addr) \
    asm volatile("ldmatrix.sync.aligned.m8n8.x4.shared.b16 {%0,%1,%2,%3}, [%4];" \
        : "=r"((r)[0]), "=r"((r)[1]), "=r"((r)[2]), "=r"((r)[3]) : "r"(addr))
#define MMA_BF16(d, a, b) \
    asm volatile("mma.sync.aligned.m16n8k16.row.col.f32.bf16.bf16.f32 " \
        "{%0,%1,%2,%3}, {%4,%5,%6,%7}, {%8,%9}, {%0,%1,%2,%3};" \
        : "+f"((d)[0]), "+f"((d)[1]), "+f"((d)[2]), "+f"((d)[3]) \
        : "r"((a)[0]), "r"((a)[1]), "r"((a)[2]), "r"((a)[3]), "r"((b)[0]), "r"((b)[1]))
#define MMA_F16(d, a, b) \
    asm volatile("mma.sync.aligned.m16n8k16.row.col.f32.f16.f16.f32 " \
        "{%0,%1,%2,%3}, {%4,%5,%6,%7}, {%8,%9}, {%0,%1,%2,%3};" \
        : "+f"((d)[0]), "+f"((d)[1]), "+f"((d)[2]), "+f"((d)[3]) \
        : "r"((a)[0]), "r"((a)[1]), "r"((a)[2]), "r"((a)[3]), "r"((b)[0]), "r"((b)[1]))
#define STS128(addr, r0, r1, r2, r3) \
    asm volatile("st.shared.v4.b32 [%0], {%1,%2,%3,%4};" \
        :: "r"(addr), "r"(r0), "r"(r1), "r"(r2), "r"(r3) : "memory")

// ============================================================================
// Kernel 0a: transpose + fp16 round: Wy[16384,1024] -> g_wf16[1024][16384]
// ============================================================================
__global__ __launch_bounds__(256) void transpose_f16(const float* __restrict__ Wy)
{
    __shared__ float T[64][65];
    const int k0 = blockIdx.x * 64;
    const int o0 = blockIdx.y * 64;
    const int tid = threadIdx.x;
    {
        int kr = tid >> 4, o4 = tid & 15;
        #pragma unroll
        for (int r = 0; r < 4; r++) {
            int k = kr + r * 16;
            float4 v = *(const float4*)&Wy[(size_t)(k0 + k) * D_OUT + o0 + o4 * 4];
            T[k][o4 * 4 + 0] = v.x;  T[k][o4 * 4 + 1] = v.y;
            T[k][o4 * 4 + 2] = v.z;  T[k][o4 * 4 + 3] = v.w;
        }
    }
    __syncthreads();
    {
        int o = tid >> 2, kq = tid & 3;
        uint32_t hv[8];
        #pragma unroll
        for (int i = 0; i < 8; i++)
            hv[i] = pack_f16f(T[kq * 16 + i * 2][o], T[kq * 16 + i * 2 + 1][o]);
        size_t dst = (size_t)(o0 + o) * KTOT + k0 + kq * 16;
        *(uint4*)&g_wf16[dst]     = make_uint4(hv[0], hv[1], hv[2], hv[3]);
        *(uint4*)&g_wf16[dst + 8] = make_uint4(hv[4], hv[5], hv[6], hv[7]);
    }
}

// ============================================================================
// Kernel 0b: by[16][1024] -> g_byf16[1024][32] fp16 (k 16..31 zero)
// ============================================================================
__global__ __launch_bounds__(256) void by_prep(const float* __restrict__ by)
{
    int o = blockIdx.x * 256 + threadIdx.x;
    if (o >= D_OUT) return;
    #pragma unroll
    for (int kp = 0; kp < 8; kp++) {
        *(uint32_t*)&g_byf16[(size_t)o * 32 + kp * 2] =
            pack_f16f(by[(size_t)(kp * 2) * D_OUT + o],
                      by[(size_t)(kp * 2 + 1) * D_OUT + o]);
    }
    #pragma unroll
    for (int kp = 8; kp < 16; kp++)
        *(uint32_t*)&g_byf16[(size_t)o * 32 + kp * 2] = 0u;
}

// ============================================================================
// Kernel 0c: Wd -> g_wd (K-major, bf16 hi/lo) — logits path
// ============================================================================
__global__ __launch_bounds__(256) void wd_prep(const float* __restrict__ Wd)
{
    const int c = blockIdx.x;
    const int n = c >> 4, j = c & 15;
    const int tid = threadIdx.x;
    const float* src = Wd + (size_t)n * (D_IN * 16) + j;
    int k = tid * 4;
    float a0 = src[(size_t)(k + 0) * 16];
    float a1 = src[(size_t)(k + 1) * 16];
    float a2 = src[(size_t)(k + 2) * 16];
    float a3 = src[(size_t)(k + 3) * 16];
    uint32_t h0 = pack_bf16(a0, a1);
    uint32_t h1 = pack_bf16(a2, a3);
    float f0 = __uint_as_float(h0 << 16);
    float f1 = __uint_as_float(h0 & 0xFFFF0000u);
    float f2 = __uint_as_float(h1 << 16);
    float f3 = __uint_as_float(h1 & 0xFFFF0000u);
    *(uint2*)&g_wd_hi[(size_t)c * D_IN + k] = make_uint2(h0, h1);
    *(uint2*)&g_wd_lo[(size_t)c * D_IN + k] =
        make_uint2(pack_bf16(a0 - f0, a1 - f1), pack_bf16(a2 - f2, a3 - f3));
}

// ============================================================================
// logits path (split-bf16, unchanged from best)
// ============================================================================
__device__ __forceinline__ void math_kh(uint32_t cb, int kh, int wm, int wn,
                                        int j, int rr, float acc[4][8][4])
{
    uint32_t afh[4][4], afl[4][4];
    #pragma unroll
    for (int t = 0; t < 4; t++) {
        int row = wm + t * 16 + ((j & 1) << 3) + rr;
        int q = kh * 2 + (j >> 1);
        LDSM4(afh[t], sw(cb, row, q));
        LDSM4(afl[t], sw(cb + 8192, row, q));
    }
    #pragma unroll
    for (int uh = 0; uh < 2; uh++) {
        uint32_t bfh[4][2], bfl[4][2];
        #pragma unroll
        for (int up = 0; up < 2; up++) {
            int u0 = uh * 4 + up * 2;
            int nrow = wn + u0 * 8 + ((j >> 1) << 3) + rr;
            int q = kh * 2 + (j & 1);
            uint32_t t4[4];
            LDSM4(t4, sw(cb + 16384, nrow, q));
            bfh[up * 2][0] = t4[0]; bfh[up * 2][1] = t4[1];
            bfh[up * 2 + 1][0] = t4[2]; bfh[up * 2 + 1][1] = t4[3];
            LDSM4(t4, sw(cb + 32768, nrow, q));
            bfl[up * 2][0] = t4[0]; bfl[up * 2][1] = t4[1];
            bfl[up * 2 + 1][0] = t4[2]; bfl[up * 2 + 1][1] = t4[3];
        }
        #pragma unroll
        for (int t = 0; t < 4; t++)
            #pragma unroll
            for (int uu = 0; uu < 4; uu++)
                MMA_BF16(acc[t][uh * 4 + uu], afh[t], bfh[uu]);
        #pragma unroll
        for (int t = 0; t < 4; t++)
            #pragma unroll
            for (int uu = 0; uu < 4; uu++)
                MMA_BF16(acc[t][uh * 4 + uu], afh[t], bfl[uu]);
        #pragma unroll
        for (int t = 0; t < 4; t++)
            #pragma unroll
            for (int uu = 0; uu < 4; uu++)
                MMA_BF16(acc[t][uh * 4 + uu], afl[t], bfh[uu]);
    }
}

#define LBUFSTRIDE 49152
#define LSMEM_TOTAL (2 * LBUFSTRIDE)
#define LSTG (D_IN / 32 / LSPLIT)

__device__ __forceinline__ void cp_b_logits(uint32_t buf, int kc, int tid)
{
    size_t off = ((size_t)tid * D_IN + (size_t)kc * 32) * 2;
    const char* sh = (const char*)g_wd_hi + off;
    const char* sl = (const char*)g_wd_lo + off;
    uint32_t bh = buf + 16384, bl = buf + 32768;
    #pragma unroll
    for (int q = 0; q < 4; q++) {
        CP_ASYNC16(sw(bh, tid, q), sh + q * 16);
        CP_ASYNC16(sw(bl, tid, q), sl + q * 16);
    }
}

__device__ __forceinline__ void gen_a_logits(uint32_t buf, const float* __restrict__ x,
                                             int bm, int kc, int tid)
{
    const int ar = tid >> 1;
    const int half = tid & 1;
    float v[16];
    const float* xp = x + (size_t)(bm + ar) * D_IN + kc * 32 + half * 16;
    #pragma unroll
    for (int q = 0; q < 4; q++) {
        float4 t4 = *(const float4*)(xp + q * 4);
        v[q * 4 + 0] = t4.x; v[q * 4 + 1] = t4.y;
        v[q * 4 + 2] = t4.z; v[q * 4 + 3] = t4.w;
    }
    #pragma unroll
    for (int q2 = 0; q2 < 2; q2++) {
        uint32_t hi4[4], lo4[4];
        #pragma unroll
        for (int i = 0; i < 4; i++) {
            float f0 = v[q2 * 8 + i * 2];
            float f1 = v[q2 * 8 + i * 2 + 1];
            uint32_t hb = pack_bf16(f0, f1);
            float fh0 = __uint_as_float(hb << 16);
            float fh1 = __uint_as_float(hb & 0xFFFF0000u);
            hi4[i] = hb;
            lo4[i] = pack_bf16(f0 - fh0, f1 - fh1);
        }
        int q = half * 2 + q2;
        STS128(sw(buf, ar, q),        hi4[0], hi4[1], hi4[2], hi4[3]);
        STS128(sw(buf + 8192, ar, q), lo4[0], lo4[1], lo4[2], lo4[3]);
    }
}

__global__ __launch_bounds__(256, 1) void logits_mma(const float* __restrict__ x)
{
    extern __shared__ char smem[];
    const uint32_t sb = smem_to_u32(smem);
    const int tid = threadIdx.x;
    const int lane = tid & 31, w = tid >> 5;
    const int ks = blockIdx.x;
    const int bm = blockIdx.y * 128;
    const int wm = (w & 1) * 64, wn = (w >> 1) * 64;
    const int kc0 = ks * LSTG;

    float acc[4][8][4];
    #pragma unroll
    for (int t = 0; t < 4; t++)
        #pragma unroll
        for (int u = 0; u < 8; u++)
            #pragma unroll
            for (int c = 0; c < 4; c++) acc[t][u][c] = 0.f;

    cp_b_logits(sb, kc0, tid);
    CP_COMMIT();
    gen_a_logits(sb, x, bm, kc0, tid);
    CP_WAIT0();
    __syncthreads();

    const int j = lane >> 3, rr = lane & 7;
    for (int s = 0; s < LSTG; s++) {
        const uint32_t cb = sb + (uint32_t)(s & 1) * LBUFSTRIDE;
        const uint32_t nb = sb + (uint32_t)((s + 1) & 1) * LBUFSTRIDE;
        const bool has_next = (s + 1 < LSTG);
        if (has_next) { cp_b_logits(nb, kc0 + s + 1, tid); CP_COMMIT(); }
        math_kh(cb, 0, wm, wn, j, rr, acc);
        if (has_next) gen_a_logits(nb, x, bm, kc0 + s + 1, tid);
        math_kh(cb, 1, wm, wn, j, rr, acc);
        if (has_next) CP_WAIT0();
        __syncthreads();
    }

    float* lp = g_lpart + (size_t)ks * (B_DIM * 256);
    #pragma unroll
    for (int t = 0; t < 4; t++) {
        int row0 = bm + wm + t * 16 + (lane >> 2);
        #pragma unroll
        for (int u = 0; u < 8; u++) {
            int col = wn + u * 8 + (lane & 3) * 2;
            *(float2*)&lp[(size_t)row0 * 256 + col] =
                make_float2(acc[t][u][0], acc[t][u][1]);
            *(float2*)&lp[(size_t)(row0 + 8) * 256 + col] =
                make_float2(acc[t][u][2], acc[t][u][3]);
        }
    }
}

// ============================================================================
// power: sum partials + bd, softmax + warp-parallel 16x16 solve
// ============================================================================
__global__ __launch_bounds__(256) void power_kernel(const float* __restrict__ bd)
{
    const int tid = threadIdx.x;
    const int lane = tid & 31;
    const int l16 = lane & 15;
    const int b = blockIdx.x * 16 + (tid >> 4);
    const float ome = 1.f - EPSV;

    float d[16];
    {
        size_t base = (size_t)b * 256 + l16 * 16;
        #pragma unroll
        for (int q = 0; q < 4; q++) {
            float4 t0 = *(const float4*)(g_lpart + base + q * 4);
            float4 t1 = *(const float4*)(g_lpart + (size_t)1 * B_DIM * 256 + base + q * 4);
            float4 t2 = *(const float4*)(g_lpart + (size_t)2 * B_DIM * 256 + base + q * 4);
            float4 t3 = *(const float4*)(g_lpart + (size_t)3 * B_DIM * 256 + base + q * 4);
            float4 bb = *(const float4*)(bd + l16 * 16 + q * 4);
            d[q * 4 + 0] = t0.x + t1.x + t2.x + t3.x + bb.x;
            d[q * 4 + 1] = t0.y + t1.y + t2.y + t3.y + bb.y;
            d[q * 4 + 2] = t0.z + t1.z + t2.z + t3.z + bb.z;
            d[q * 4 + 3] = t0.w + t1.w + t2.w + t3.w + bb.w;
        }
        float mx = d[0];
        #pragma unroll
        for (int j = 1; j < 16; j++) mx = fmaxf(mx, d[j]);
        float s = 0.f;
        #pragma unroll
        for (int j = 0; j < 16; j++) { d[j] = expf(d[j] - mx); s += d[j]; }
        float inv = 1.f / s;
        #pragma unroll
        for (int j = 0; j < 16; j++) d[j] *= inv;
    }

    #pragma unroll
    for (int m = 1; m < 16; m <<= 1) {
        float u[16];
        #pragma unroll
        for (int i = 0; i < 16; i++)
            u[i] = __shfl_xor_sync(0xffffffffu, d[i ^ m], m);
        #pragma unroll
        for (int i = 0; i < 16; i++)
            if ((i & m) != (l16 & m)) d[i] = u[i];
    }

    float diag = 0.f;
    #pragma unroll
    for (int i = 0; i < 16; i++)
        if (i == l16) diag = d[i];

    float row[17];
    #pragma unroll
    for (int n = 0; n < 16; n++)
        row[n] = (n == l16) ? 1.f : -ome * d[n];
    row[16] = 1.f;

    #pragma unroll
    for (int p = 0; p < 16; p++) {
        float pivot = __shfl_sync(0xffffffffu, row[p], p, 16);
        float inv = 1.f / pivot;
        float f = row[p];
        #pragma unroll
        for (int c = p; c < 17; c++) {
            float pc = __shfl_sync(0xffffffffu, row[c], p, 16) * inv;
            if (l16 == p)      row[c] = pc;
            else if (l16 > p)  row[c] -= f * pc;
        }
    }

    float s = row[16];
    float z = 0.f;
    #pragma unroll
    for (int r = 15; r >= 0; r--) {
        float zr = __shfl_sync(0xffffffffu, s, r, 16);
        if (l16 == r) z = zr;
        if (l16 < r)  s -= row[r] * zr;
    }

    float zs = z;
    #pragma unroll
    for (int m = 8; m >= 1; m >>= 1)
        zs += __shfl_xor_sync(0xffffffffu, zs, m);
    float z16 = 1.f + EPSV * zs;
    float add = z16 * (1.f / 16.f) - (1.f / 16.f);
    g_power[(size_t)b * 16 + l16] = z * ome * diag + add;
}

// ============================================================================
// main_gemm: fp16 single-pass (A single plane, B single plane).
// 512 threads, 16 warps, warp tile 32x64, CTA 128x256, K-chunk 32.
// Buffer (24KB): A[8K] B[16K]
// ============================================================================
#define MBUFSTRIDE 24576
#define MSMEM_TOTAL (2 * MBUFSTRIDE)
#define NSTG 513

__device__ __forceinline__ void cp_b_main(uint32_t buf, int bn, int t, int tid)
{
    const int row = tid >> 1;
    const int q0 = (tid & 1) * 2;
    const char* sh;
    if (t < 512) {
        size_t off = ((size_t)(bn + row) * KTOT +
                      (size_t)(t & 15) * 1024 + (size_t)(t >> 4) * 32) * 2;
        sh = (const char*)g_wf16 + off;
    } else {
        sh = (const char*)g_byf16 + (size_t)(bn + row) * 64;
    }
    uint32_t bb = buf + 8192;
    CP_ASYNC16(sw(bb, row, q0),     sh + q0 * 16);
    CP_ASYNC16(sw(bb, row, q0 + 1), sh + q0 * 16 + 16);
}

// A gen: a = fp16(p*x), single plane. Thread: row tid>>2, granule tid&3.
__device__ __forceinline__ void gen_a_main(uint32_t buf, int bm, int t, int tid,
                                           const float* xv)
{
    const int ar = tid >> 2;
    const int sub = tid & 3;
    float v[8];
    float p;
    if (t < 512) {
        const int n = t & 15;
        p = g_power[(size_t)(bm + ar) * 16 + n];
        #pragma unroll
        for (int i = 0; i < 8; i++) v[i] = xv[i];
    } else {
        p = 1.f;
        if (sub < 2) {
            const float* pp = &g_power[(size_t)(bm + ar) * 16 + sub * 8];
            float4 a = *(const float4*)pp;
            float4 b = *(const float4*)(pp + 4);
            v[0] = a.x; v[1] = a.y; v[2] = a.z; v[3] = a.w;
            v[4] = b.x; v[5] = b.y; v[6] = b.z; v[7] = b.w;
        } else {
            #pragma unroll
            for (int i = 0; i < 8; i++) v[i] = 0.f;
        }
    }
    uint32_t hv[4];
    #pragma unroll
    for (int i = 0; i < 4; i++)
        hv[i] = pack_f16f(v[i * 2] * p, v[i * 2 + 1] * p);
    STS128(sw(buf, ar, sub), hv[0], hv[1], hv[2], hv[3]);
}

// one k16 math step, warp tile 32x64, single fp16 pass
__device__ __forceinline__ void math_f16(uint32_t cb, int kh, int wm, int wn,
                                         int j, int rr, float acc[2][8][4])
{
    uint32_t af[2][4];
    #pragma unroll
    for (int t = 0; t < 2; t++) {
        int row = wm + t * 16 + ((j & 1) << 3) + rr;
        int q = kh * 2 + (j >> 1);
        LDSM4(af[t], sw(cb, row, q));
    }
    #pragma unroll
    for (int uh = 0; uh < 2; uh++) {
        uint32_t bf[4][2];
        #pragma unroll
        for (int up = 0; up < 2; up++) {
            int u0 = uh * 4 + up * 2;
            int nrow = wn + u0 * 8 + ((j >> 1) << 3) + rr;
            int q = kh * 2 + (j & 1);
            uint32_t t4[4];
            LDSM4(t4, sw(cb + 8192, nrow, q));
            bf[up * 2][0] = t4[0]; bf[up * 2][1] = t4[1];
            bf[up * 2 + 1][0] = t4[2]; bf[up * 2 + 1][1] = t4[3];
        }
        #pragma unroll
        for (int t = 0; t < 2; t++)
            #pragma unroll
            for (int uu = 0; uu < 4; uu++)
                MMA_F16(acc[t][uh * 4 + uu], af[t], bf[uu]);
    }
}

__global__ __launch_bounds__(512, 1) void main_gemm(
    const float* __restrict__ x, float* __restrict__ out)
{
    extern __shared__ char smem[];
    const uint32_t sb = smem_to_u32(smem);
    const int tid = threadIdx.x;
    const int lane = tid & 31, w = tid >> 5;
    const int bm = blockIdx.y * 128;
    const int bn = blockIdx.x * 256;
    const int wm = (w & 3) * 32, wn = (w >> 2) * 64;

    float acc[2][8][4];
    #pragma unroll
    for (int t = 0; t < 2; t++)
        #pragma unroll
        for (int u = 0; u < 8; u++)
            #pragma unroll
            for (int c = 0; c < 4; c++) acc[t][u][c] = 0.f;

    const int ar = tid >> 2;
    const float* xbase = x + (size_t)(bm + ar) * D_IN + (tid & 3) * 8;
    float xv[8];
    {
        float4 a = *(const float4*)xbase;
        float4 b = *(const float4*)(xbase + 4);
        xv[0]=a.x; xv[1]=a.y; xv[2]=a.z; xv[3]=a.w;
        xv[4]=b.x; xv[5]=b.y; xv[6]=b.z; xv[7]=b.w;
    }

    cp_b_main(sb, bn, 0, tid);
    CP_COMMIT();
    gen_a_main(sb, bm, 0, tid, xv);
    CP_WAIT0();
    __syncthreads();

    const int j = lane >> 3, rr = lane & 7;

    for (int s = 0; s < NSTG; s++) {
        const uint32_t cb = sb + (uint32_t)(s & 1) * MBUFSTRIDE;
        const uint32_t nb = sb + (uint32_t)((s + 1) & 1) * MBUFSTRIDE;
        const bool has_next = (s + 1 < NSTG);

        if (has_next) {
            cp_b_main(nb, bn, s + 1, tid);
            CP_COMMIT();
        }
        math_f16(cb, 0, wm, wn, j, rr, acc);
        if (has_next) {
            const int t = s + 1;
            if ((t & 15) == 0 && t < 512) {
                const float* xp = xbase + (t >> 4) * 32;
                float4 a = *(const float4*)xp;
                float4 b = *(const float4*)(xp + 4);
                xv[0]=a.x; xv[1]=a.y; xv[2]=a.z; xv[3]=a.w;
                xv[4]=b.x; xv[5]=b.y; xv[6]=b.z; xv[7]=b.w;
            }
            gen_a_main(nb, bm, t, tid, xv);
        }
        math_f16(cb, 1, wm, wn, j, rr, acc);
        if (has_next) CP_WAIT0();
        __syncthreads();
    }

    #pragma unroll
    for (int t = 0; t < 2; t++) {
        int row0 = bm + wm + t * 16 + (lane >> 2);
        #pragma unroll
        for (int u = 0; u < 8; u++) {
            int col = bn + wn + u * 8 + (lane & 3) * 2;
            *(float2*)&out[(size_t)row0 * D_OUT + col] =
                make_float2(acc[t][u][0], acc[t][u][1]);
            *(float2*)&out[(size_t)(row0 + 8) * D_OUT + col] =
                make_float2(acc[t][u][2], acc[t][u][3]);
        }
    }
}

// ============================================================================
extern "C" void kernel_launch(void* const* d_in, const int* in_sizes, int n_in,
                              void* d_out, int out_size)
{
    const float* x  = (const float*)d_in[0];
    const float* Wy = (const float*)d_in[1];
    const float* by = (const float*)d_in[2];
    const float* Wd = (const float*)d_in[3];
    const float* bd = (const float*)d_in[4];
    float* out = (float*)d_out;

    cudaFuncSetAttribute(main_gemm, cudaFuncAttributeMaxDynamicSharedMemorySize,
                         MSMEM_TOTAL);
    cudaFuncSetAttribute(logits_mma, cudaFuncAttributeMaxDynamicSharedMemorySize,
                         LSMEM_TOTAL);

    transpose_f16<<<dim3(KTOT / 64, D_OUT / 64), 256>>>(Wy);
    by_prep<<<D_OUT / 256, 256>>>(by);
    wd_prep<<<256, 256>>>(Wd);
    logits_mma<<<dim3(LSPLIT, B_DIM / 128), 256, LSMEM_TOTAL>>>(x);
    power_kernel<<<B_DIM / 16, 256>>>(bd);
    main_gemm<<<dim3(D_OUT / 256, B_DIM / 128), 512, MSMEM_TOTAL>>>(x, out);
}